// round 8
// baseline (speedup 1.0000x reference)
#include <cuda_runtime.h>
#include <cuda_bf16.h>
#include <math.h>
#include <stdint.h>

// Problem constants (fixed by the reference)
#define NN 50000
#define EE 200000
#define DD 384
#define HH 2
#define DHH 192

#define SCAN_BLK 1024
#define NSCAN ((NN + SCAN_BLK - 1) / SCAN_BLK)   // 49

// ---------------- device scratch (allocation-free requirement) ----------------
__device__ float g_q[(size_t)NN * DD];
__device__ float g_k[(size_t)NN * DD];
__device__ float g_v[(size_t)NN * DD];
__device__ float g_tmp[(size_t)NN * DD];

__device__ int   g_deg[NN];
__device__ int   g_rowptr[NN + 1];
__device__ int   g_cursor[NN];
__device__ int   g_blocksum[NSCAN];
__device__ int   g_esrc[EE];
__device__ float g_eea[EE];

__device__ __nv_bfloat16 g_emb_hi[(size_t)NN * DD];
__device__ __nv_bfloat16 g_emb_lo[(size_t)NN * DD];
__device__ __nv_bfloat16 g_agg_hi[(size_t)NN * DD];
__device__ __nv_bfloat16 g_agg_lo[(size_t)NN * DD];
__device__ __nv_bfloat16 g_wt_hi[(size_t)3 * DD * DD];   // [WQ|WK|WV]^T  [1152(N), 384(K)]
__device__ __nv_bfloat16 g_wt_lo[(size_t)3 * DD * DD];
__device__ __nv_bfloat16 g_wo_hi[(size_t)DD * DD];       // WO^T [384, 384]
__device__ __nv_bfloat16 g_wo_lo[(size_t)DD * DD];

// ---------------- PTX helpers (baseline features only; PTX target is compute_103) ----------------
__device__ __forceinline__ uint32_t smem_to_u32(const void* p) {
    uint32_t a;
    asm("{ .reg .u64 t; cvta.to.shared.u64 t, %1; cvt.u32.u64 %0, t; }" : "=r"(a) : "l"(p));
    return a;
}
__device__ __forceinline__ void ldsm_x4(uint32_t* r, uint32_t addr) {
    asm volatile("ldmatrix.sync.aligned.m8n8.x4.shared.b16 {%0,%1,%2,%3}, [%4];"
        : "=r"(r[0]), "=r"(r[1]), "=r"(r[2]), "=r"(r[3]) : "r"(addr));
}
__device__ __forceinline__ void mma_bf16(float* c, const uint32_t* a, const uint32_t* b) {
    asm volatile(
        "mma.sync.aligned.m16n8k16.row.col.f32.bf16.bf16.f32 "
        "{%0,%1,%2,%3}, {%4,%5,%6,%7}, {%8,%9}, {%0,%1,%2,%3};"
        : "+f"(c[0]), "+f"(c[1]), "+f"(c[2]), "+f"(c[3])
        : "r"(a[0]), "r"(a[1]), "r"(a[2]), "r"(a[3]), "r"(b[0]), "r"(b[1]));
}
__device__ __forceinline__ void cp16(uint32_t dst, const void* src, bool valid) {
    int sz = valid ? 16 : 0;
    asm volatile("cp.async.cg.shared.global [%0], [%1], 16, %2;"
        :: "r"(dst), "l"(src), "r"(sz) : "memory");
}

// smem geometry: 4 operand arrays (Ahi,Alo,Bhi,Blo), 128 rows x 112B pitch (48 K bf16 + pad),
// double-buffered. 112 KB/CTA -> 2 CTAs/SM.
#define KC    48             // K elements per stage
#define NSTG  (DD / KC)      // 8 stages
#define PITCH 112
#define ARR   14336          // 128 * 112
#define STG   57344          // 4 * ARR
#define SM_TOTAL (2 * STG)   // 114688

// ---------------- bf16x3 HMMA GEMM ----------------
// C[m, colBase+n] = sum_k A[m,k] * Bt[bx*128+n, k]  (+resid)
__global__ __launch_bounds__(256)
void gemm_tc(const __nv_bfloat16* __restrict__ Ahi, const __nv_bfloat16* __restrict__ Alo,
             const __nv_bfloat16* __restrict__ Bhi, const __nv_bfloat16* __restrict__ Blo,
             float* __restrict__ C0, float* __restrict__ C1, float* __restrict__ C2,
             int M, const float* __restrict__ resid)
{
    extern __shared__ char smem[];
    const uint32_t sb = smem_to_u32(smem);
    const int tid = threadIdx.x;
    const int wid = tid >> 5;
    const int lane = tid & 31;
    const int warp_m = wid & 1;
    const int warp_n = wid >> 1;
    const int rowBase = blockIdx.y * 128;
    const int mat = blockIdx.x / 3;
    const int colBase = (blockIdx.x % 3) * 128;
    const int btRowBase = blockIdx.x * 128;
    float* C = (mat == 0) ? C0 : (mat == 1 ? C1 : C2);

    float acc[4][4][4];
#pragma unroll
    for (int i = 0; i < 4; i++)
#pragma unroll
        for (int j = 0; j < 4; j++)
#pragma unroll
            for (int l = 0; l < 4; l++) acc[i][j][l] = 0.0f;

    const __nv_bfloat16* srcA[2] = { Ahi, Alo };
    const __nv_bfloat16* srcB[2] = { Bhi, Blo };

    // stage = 4 arrays x 128 rows x 6 chunks of 16B  => 3072 cp16, 12 per thread
    auto load_stage = [&](int buf, int s) {
        const int k0 = s * KC;
#pragma unroll
        for (int i = 0; i < 12; i++) {
            int id = i * 256 + tid;          // 0..3071
            int arr = id / 768;              // 0..3
            int rem = id - arr * 768;
            int row = rem / 6;               // 0..127
            int c = rem - row * 6;           // 16B chunk 0..5
            uint32_t dst = sb + buf * STG + arr * ARR + row * PITCH + c * 16;
            const __nv_bfloat16* src;
            bool valid = true;
            if (arr < 2) {
                int gRow = rowBase + row;
                valid = (gRow < M);
                int gr = valid ? gRow : 0;
                src = srcA[arr] + (size_t)gr * DD + k0 + c * 8;
            } else {
                src = srcB[arr - 2] + (size_t)(btRowBase + row) * DD + k0 + c * 8;
            }
            cp16(dst, src, valid);
        }
        asm volatile("cp.async.commit_group;" ::: "memory");
    };

    load_stage(0, 0);

    for (int s = 0; s < NSTG; s++) {
        asm volatile("cp.async.wait_group 0;" ::: "memory");
        __syncthreads();                         // single barrier per stage
        if (s + 1 < NSTG) load_stage((s + 1) & 1, s + 1);   // overlaps compute(s)

        const uint32_t st = sb + (s & 1) * STG;
#pragma unroll
        for (int kk = 0; kk < 3; kk++) {
            uint32_t ah[4][4], al[4][4], bh[2][4], bl[2][4];
            const int arow = warp_m * 64;
#pragma unroll
            for (int mt = 0; mt < 4; mt++) {
                uint32_t addr = st + (uint32_t)((arow + mt * 16 + (lane & 15)) * PITCH
                              + kk * 32 + ((lane >> 4) & 1) * 16);
                ldsm_x4(ah[mt], addr);
                ldsm_x4(al[mt], addr + ARR);
            }
#pragma unroll
            for (int p = 0; p < 2; p++) {
                int grp = lane >> 3;
                int row = warp_n * 32 + (p * 2 + (grp >> 1)) * 8 + (lane & 7);
                uint32_t addr = st + 2 * ARR + (uint32_t)(row * PITCH
                              + kk * 32 + (grp & 1) * 16);
                ldsm_x4(bh[p], addr);
                ldsm_x4(bl[p], addr + ARR);
            }
#pragma unroll
            for (int mt = 0; mt < 4; mt++) {
#pragma unroll
                for (int nt = 0; nt < 4; nt++) {
                    const uint32_t* B2h = &bh[nt >> 1][(nt & 1) * 2];
                    const uint32_t* B2l = &bl[nt >> 1][(nt & 1) * 2];
                    mma_bf16(acc[mt][nt], ah[mt], B2h);
                    mma_bf16(acc[mt][nt], ah[mt], B2l);
                    mma_bf16(acc[mt][nt], al[mt], B2h);
                }
            }
        }
    }

#pragma unroll
    for (int mt = 0; mt < 4; mt++) {
        int r0 = rowBase + warp_m * 64 + mt * 16 + (lane >> 2);
#pragma unroll
        for (int nt = 0; nt < 4; nt++) {
            int col = colBase + warp_n * 32 + nt * 8 + (lane & 3) * 2;
#pragma unroll
            for (int half = 0; half < 2; half++) {
                int r = r0 + half * 8;
                if (r >= M) continue;
                size_t off = (size_t)r * DD + col;
                float2 v = make_float2(acc[mt][nt][half * 2], acc[mt][nt][half * 2 + 1]);
                if (resid) {
                    float2 rv = *reinterpret_cast<const float2*>(resid + off);
                    v.x += rv.x; v.y += rv.y;
                }
                *reinterpret_cast<float2*>(C + off) = v;
            }
        }
    }
}

// ---------------- conversions ----------------
// vectorized: 4 elements per thread
__global__ __launch_bounds__(256) void conv_emb(const float* __restrict__ emb) {
    int idx = blockIdx.x * 256 + threadIdx.x;
    if (idx >= NN * DD / 4) return;
    float4 x = reinterpret_cast<const float4*>(emb)[idx];
    __nv_bfloat16 h0 = __float2bfloat16(x.x);
    __nv_bfloat16 h1 = __float2bfloat16(x.y);
    __nv_bfloat16 h2 = __float2bfloat16(x.z);
    __nv_bfloat16 h3 = __float2bfloat16(x.w);
    __nv_bfloat162 hi01, hi23, lo01, lo23;
    hi01.x = h0; hi01.y = h1; hi23.x = h2; hi23.y = h3;
    lo01.x = __float2bfloat16(x.x - __bfloat162float(h0));
    lo01.y = __float2bfloat16(x.y - __bfloat162float(h1));
    lo23.x = __float2bfloat16(x.z - __bfloat162float(h2));
    lo23.y = __float2bfloat16(x.w - __bfloat162float(h3));
    uint2 hiv = make_uint2(*reinterpret_cast<uint32_t*>(&hi01), *reinterpret_cast<uint32_t*>(&hi23));
    uint2 lov = make_uint2(*reinterpret_cast<uint32_t*>(&lo01), *reinterpret_cast<uint32_t*>(&lo23));
    reinterpret_cast<uint2*>(g_emb_hi)[idx] = hiv;
    reinterpret_cast<uint2*>(g_emb_lo)[idx] = lov;
}

__global__ __launch_bounds__(256) void conv_weights(
    const float* __restrict__ WQ, const float* __restrict__ WK,
    const float* __restrict__ WV, const float* __restrict__ WO)
{
    int idx = blockIdx.x * 256 + threadIdx.x;
    if (idx >= 4 * DD * DD) return;
    int mat = idx / (DD * DD);
    int rem = idx - mat * (DD * DD);
    int n = rem / DD;
    int k = rem - n * DD;
    const float* W = (mat == 0) ? WQ : (mat == 1 ? WK : (mat == 2 ? WV : WO));
    float x = W[(size_t)k * DD + n];
    __nv_bfloat16 hi = __float2bfloat16(x);
    __nv_bfloat16 lo = __float2bfloat16(x - __bfloat162float(hi));
    if (mat < 3) {
        size_t o = (size_t)mat * DD * DD + (size_t)n * DD + k;
        g_wt_hi[o] = hi; g_wt_lo[o] = lo;
    } else {
        size_t o = (size_t)n * DD + k;
        g_wo_hi[o] = hi; g_wo_lo[o] = lo;
    }
}

// ---------------- CSR build (side stream) ----------------
__global__ __launch_bounds__(256) void zero_deg() {
    int i = blockIdx.x * 256 + threadIdx.x;
    if (i < NN) g_deg[i] = 0;
}

__global__ __launch_bounds__(256) void hist_kernel(const int* __restrict__ dst) {
    int e = blockIdx.x * 256 + threadIdx.x;
    if (e < EE) atomicAdd(&g_deg[dst[e]], 1);
}

__device__ __forceinline__ int warp_incl_scan(int x, int lane) {
#pragma unroll
    for (int off = 1; off < 32; off <<= 1) {
        int v = __shfl_up_sync(0xffffffffu, x, off);
        if (lane >= off) x += v;
    }
    return x;
}

__global__ __launch_bounds__(1024) void scanA() {
    __shared__ int swarp[32];
    const int tid = threadIdx.x;
    const int w = tid >> 5, lane = tid & 31;
    int idx = blockIdx.x * 1024 + tid;
    int x = (idx < NN) ? g_deg[idx] : 0;
    int incl = warp_incl_scan(x, lane);
    if (lane == 31) swarp[w] = incl;
    __syncthreads();
    if (w == 0) {
        int t = swarp[lane];
        t = warp_incl_scan(t, lane);
        swarp[lane] = t;
    }
    __syncthreads();
    int woff = (w > 0) ? swarp[w - 1] : 0;
    incl += woff;
    if (idx < NN) g_rowptr[idx] = incl;
    if (tid == 1023) g_blocksum[blockIdx.x] = incl;
}

__global__ __launch_bounds__(64) void scanB() {
    __shared__ int sh[64];
    const int tid = threadIdx.x;
    int v = (tid < NSCAN) ? g_blocksum[tid] : 0;
    sh[tid] = v;
    for (int off = 1; off < 64; off <<= 1) {
        __syncthreads();
        int t = (tid >= off) ? sh[tid - off] : 0;
        __syncthreads();
        sh[tid] += t;
    }
    __syncthreads();
    if (tid < NSCAN) g_blocksum[tid] = sh[tid] - v;  // exclusive
    if (tid == 63) g_rowptr[NN] = sh[63];
}

__global__ __launch_bounds__(1024) void scanC() {
    int idx = blockIdx.x * 1024 + threadIdx.x;
    if (idx >= NN) return;
    int ex = g_blocksum[blockIdx.x] + g_rowptr[idx] - g_deg[idx];
    g_rowptr[idx] = ex;
    g_cursor[idx] = ex;
}

__global__ __launch_bounds__(256) void scatter_kernel(
    const int* __restrict__ src, const int* __restrict__ dst,
    const float* __restrict__ eattr)
{
    int e = blockIdx.x * 256 + threadIdx.x;
    if (e >= EE) return;
    int t = dst[e];
    int pos = atomicAdd(&g_cursor[t], 1);
    g_esrc[pos] = src[e];
    g_eea[pos] = eattr[e];
}

// ---------------- fused attention aggregate: warp per (node, head) ----------------
__global__ __launch_bounds__(256) void node_fused(const float* __restrict__ WE) {
    const int gw = blockIdx.x * 8 + (threadIdx.x >> 5);
    const int n = gw >> 1;
    if (n >= NN) return;
    const int h = gw & 1;
    const int hb = h * DHH;
    const int lane = threadIdx.x & 31;

    float qv[6], we[6];
    const float* qrow = g_q + (size_t)n * DD + hb;
    const float* werow = WE + hb;
#pragma unroll
    for (int j = 0; j < 6; j++) {
        int d = lane + 32 * j;
        qv[j] = qrow[d];
        we[j] = werow[d];
    }

    // qe = q_h . WE_h
    float qe = 0.f;
#pragma unroll
    for (int j = 0; j < 6; j++) qe += qv[j] * we[j];
#pragma unroll
    for (int o = 16; o > 0; o >>= 1) qe += __shfl_xor_sync(0xffffffffu, qe, o);

    const int beg = g_rowptr[n];
    const int end = g_rowptr[n + 1];

    float m0 = -3.0e38f, den = 0.f, sexa = 0.f;
    float acc[6];
#pragma unroll
    for (int j = 0; j < 6; j++) acc[j] = 0.f;

    const float SCL = 0.07216878364870323f;  // 1/sqrt(192)

    for (int i = beg; i < end; i++) {
        const int s = g_esrc[i];
        const float ea = g_eea[i];
        const float* krow = g_k + (size_t)s * DD + hb;
        const float* vrow = g_v + (size_t)s * DD + hb;

        float kv[6], vv[6];
#pragma unroll
        for (int j = 0; j < 6; j++) {
            int d = lane + 32 * j;
            kv[j] = krow[d];
            vv[j] = vrow[d];
        }
        float ds = 0.f;
#pragma unroll
        for (int j = 0; j < 6; j++) ds += qv[j] * kv[j];
#pragma unroll
        for (int o = 16; o > 0; o >>= 1) ds += __shfl_xor_sync(0xffffffffu, ds, o);
        float s0 = (ds + ea * qe) * SCL;

        float nm = fmaxf(m0, s0);
        float sc = expf(m0 - nm);
        float ex = expf(s0 - nm);
        den = den * sc + ex;
        sexa = sexa * sc + ex * ea;
#pragma unroll
        for (int j = 0; j < 6; j++) acc[j] = acc[j] * sc + ex * vv[j];
        m0 = nm;
    }

    const float inv = 1.0f / (den + 1e-16f);
    size_t base = (size_t)n * DD + hb;
#pragma unroll
    for (int j = 0; j < 6; j++) {
        int d = lane + 32 * j;
        float o0 = (acc[j] + sexa * we[j]) * inv;
        __nv_bfloat16 hi = __float2bfloat16(o0);
        g_agg_hi[base + d] = hi;
        g_agg_lo[base + d] = __float2bfloat16(o0 - __bfloat162float(hi));
    }
}

// ---------------- layernorm: warp per row, float4 ----------------
__global__ __launch_bounds__(256) void ln_kernel(
    const float* __restrict__ gw, const float* __restrict__ bw,
    float* __restrict__ out)
{
    const int n = blockIdx.x * 8 + (threadIdx.x >> 5);
    if (n >= NN) return;
    const int lane = threadIdx.x & 31;
    const float4* x = reinterpret_cast<const float4*>(g_tmp + (size_t)n * DD);
    float4 v[3];
    float su = 0.f, sq = 0.f;
#pragma unroll
    for (int j = 0; j < 3; j++) {
        v[j] = x[lane + 32 * j];
        su += v[j].x + v[j].y + v[j].z + v[j].w;
        sq += v[j].x * v[j].x + v[j].y * v[j].y + v[j].z * v[j].z + v[j].w * v[j].w;
    }
#pragma unroll
    for (int o = 16; o > 0; o >>= 1) {
        su += __shfl_xor_sync(0xffffffffu, su, o);
        sq += __shfl_xor_sync(0xffffffffu, sq, o);
    }
    float mu = su * (1.0f / DD);
    float var = sq * (1.0f / DD) - mu * mu;
    float inv = rsqrtf(var + 1e-5f);
    const float4* g4 = reinterpret_cast<const float4*>(gw);
    const float4* b4 = reinterpret_cast<const float4*>(bw);
    float4* o4 = reinterpret_cast<float4*>(out + (size_t)n * DD);
#pragma unroll
    for (int j = 0; j < 3; j++) {
        float4 g = g4[lane + 32 * j];
        float4 b = b4[lane + 32 * j];
        float4 r;
        r.x = (v[j].x - mu) * inv * g.x + b.x;
        r.y = (v[j].y - mu) * inv * g.y + b.y;
        r.z = (v[j].z - mu) * inv * g.z + b.z;
        r.w = (v[j].w - mu) * inv * g.w + b.w;
        o4[lane + 32 * j] = r;
    }
}

// ---------------- launch ----------------
extern "C" void kernel_launch(void* const* d_in, const int* in_sizes, int n_in,
                              void* d_out, int out_size)
{
    const float* emb   = (const float*)d_in[0];
    const int*   eidx  = (const int*)  d_in[1];
    const float* eattr = (const float*)d_in[2];
    const float* WQ    = (const float*)d_in[3];
    const float* WK    = (const float*)d_in[4];
    const float* WV    = (const float*)d_in[5];
    const float* WE    = (const float*)d_in[6];
    const float* WO    = (const float*)d_in[7];
    const float* ln_g  = (const float*)d_in[8];
    const float* ln_b  = (const float*)d_in[9];
    float* out = (float*)d_out;

    const int* src = eidx;
    const int* dst = eidx + EE;

    static bool inited = false;
    static cudaStream_t s_side;
    static cudaEvent_t ev_fork, ev_join, ev_w;
    if (!inited) {
        cudaFuncSetAttribute(gemm_tc, cudaFuncAttributeMaxDynamicSharedMemorySize, SM_TOTAL);
        cudaStreamCreateWithFlags(&s_side, cudaStreamNonBlocking);
        cudaEventCreateWithFlags(&ev_fork, cudaEventDisableTiming);
        cudaEventCreateWithFlags(&ev_join, cudaEventDisableTiming);
        cudaEventCreateWithFlags(&ev_w, cudaEventDisableTiming);
        inited = true;
    }

    float *dq, *dk, *dv, *dtmp;
    __nv_bfloat16 *dembh, *dembl, *daggh, *daggl, *dwth, *dwtl, *dwoh, *dwol;
    cudaGetSymbolAddress((void**)&dq,    g_q);
    cudaGetSymbolAddress((void**)&dk,    g_k);
    cudaGetSymbolAddress((void**)&dv,    g_v);
    cudaGetSymbolAddress((void**)&dtmp,  g_tmp);
    cudaGetSymbolAddress((void**)&dembh, g_emb_hi);
    cudaGetSymbolAddress((void**)&dembl, g_emb_lo);
    cudaGetSymbolAddress((void**)&daggh, g_agg_hi);
    cudaGetSymbolAddress((void**)&daggl, g_agg_lo);
    cudaGetSymbolAddress((void**)&dwth,  g_wt_hi);
    cudaGetSymbolAddress((void**)&dwtl,  g_wt_lo);
    cudaGetSymbolAddress((void**)&dwoh,  g_wo_hi);
    cudaGetSymbolAddress((void**)&dwol,  g_wo_lo);

    // ---- fork: weights conversion + CSR build on side stream ----
    cudaEventRecord(ev_fork, 0);
    cudaStreamWaitEvent(s_side, ev_fork, 0);
    conv_weights<<<(4 * DD * DD + 255) / 256, 256, 0, s_side>>>(WQ, WK, WV, WO);
    cudaEventRecord(ev_w, s_side);
    zero_deg<<<(NN + 255) / 256, 256, 0, s_side>>>();
    hist_kernel<<<(EE + 255) / 256, 256, 0, s_side>>>(dst);
    scanA<<<NSCAN, 1024, 0, s_side>>>();
    scanB<<<1, 64, 0, s_side>>>();
    scanC<<<NSCAN, 1024, 0, s_side>>>();
    scatter_kernel<<<(EE + 255) / 256, 256, 0, s_side>>>(src, dst, eattr);
    cudaEventRecord(ev_join, s_side);

    // ---- main stream: emb conversion + QKV projections ----
    conv_emb<<<(NN * DD / 4 + 255) / 256, 256>>>(emb);
    cudaStreamWaitEvent(0, ev_w, 0);

    const int MT = (NN + 127) / 128;
    gemm_tc<<<dim3(9, MT), 256, SM_TOTAL>>>(dembh, dembl, dwth, dwtl,
                                            dq, dk, dv, NN, nullptr);

    // ---- join, then fused attention ----
    cudaStreamWaitEvent(0, ev_join, 0);
    node_fused<<<(2 * NN + 7) / 8, 256>>>(WE);

    // output projection + residual
    gemm_tc<<<dim3(3, MT), 256, SM_TOTAL>>>(daggh, daggl, dwoh, dwol,
                                            dtmp, dtmp, dtmp, NN, emb);

    // layernorm -> out
    ln_kernel<<<(NN + 7) / 8, 256>>>(ln_g, ln_b, out);
}

// round 9
// speedup vs baseline: 1.1388x; 1.1388x over previous
#include <cuda_runtime.h>
#include <cuda_bf16.h>
#include <math.h>
#include <stdint.h>

// Problem constants (fixed by the reference)
#define NN 50000
#define EE 200000
#define DD 384
#define HH 2
#define DHH 192

#define SCAN_BLK 1024
#define NSCAN ((NN + SCAN_BLK - 1) / SCAN_BLK)   // 49

// ---------------- device scratch (allocation-free requirement) ----------------
__device__ float g_q[(size_t)NN * DD];
__device__ float g_k[(size_t)NN * DD];
__device__ float g_v[(size_t)NN * DD];
__device__ float g_tmp[(size_t)NN * DD];

__device__ int   g_deg[NN];
__device__ int   g_rowptr[NN + 1];
__device__ int   g_cursor[NN];
__device__ int   g_blocksum[NSCAN];
__device__ int   g_esrc[EE];
__device__ float g_eea[EE];

__device__ __nv_bfloat16 g_emb_hi[(size_t)NN * DD];
__device__ __nv_bfloat16 g_emb_lo[(size_t)NN * DD];
__device__ __nv_bfloat16 g_agg_hi[(size_t)NN * DD];
__device__ __nv_bfloat16 g_agg_lo[(size_t)NN * DD];
__device__ __nv_bfloat16 g_wt_hi[(size_t)3 * DD * DD];   // [WQ|WK|WV]^T  [1152(N), 384(K)]
__device__ __nv_bfloat16 g_wt_lo[(size_t)3 * DD * DD];
__device__ __nv_bfloat16 g_wo_hi[(size_t)DD * DD];       // WO^T [384, 384]
__device__ __nv_bfloat16 g_wo_lo[(size_t)DD * DD];

// ---------------- PTX helpers (baseline features only; PTX target is compute_103) ----------------
__device__ __forceinline__ uint32_t smem_to_u32(const void* p) {
    uint32_t a;
    asm("{ .reg .u64 t; cvta.to.shared.u64 t, %1; cvt.u32.u64 %0, t; }" : "=r"(a) : "l"(p));
    return a;
}
__device__ __forceinline__ void ldsm_x4(uint32_t* r, uint32_t addr) {
    asm volatile("ldmatrix.sync.aligned.m8n8.x4.shared.b16 {%0,%1,%2,%3}, [%4];"
        : "=r"(r[0]), "=r"(r[1]), "=r"(r[2]), "=r"(r[3]) : "r"(addr));
}
__device__ __forceinline__ void mma_bf16(float* c, const uint32_t* a, const uint32_t* b) {
    asm volatile(
        "mma.sync.aligned.m16n8k16.row.col.f32.bf16.bf16.f32 "
        "{%0,%1,%2,%3}, {%4,%5,%6,%7}, {%8,%9}, {%0,%1,%2,%3};"
        : "+f"(c[0]), "+f"(c[1]), "+f"(c[2]), "+f"(c[3])
        : "r"(a[0]), "r"(a[1]), "r"(a[2]), "r"(a[3]), "r"(b[0]), "r"(b[1]));
}
__device__ __forceinline__ void cp16(uint32_t dst, const void* src, bool valid) {
    int sz = valid ? 16 : 0;
    asm volatile("cp.async.cg.shared.global [%0], [%1], 16, %2;"
        :: "r"(dst), "l"(src), "r"(sz) : "memory");
}

// smem geometry: 4 operand arrays (Ahi,Alo,Bhi,Blo), 128 rows x 80B pitch, double-buffered
// 80 KB/CTA -> 2 CTAs/SM (R7 config, measured best)
#define PITCH 80
#define ARR   10240          // 128 * 80
#define STG   40960          // 4 * ARR
#define SM_TOTAL (2 * STG)   // 81920

// ---------------- bf16x3 HMMA GEMM ----------------
// C[m, colBase+n] = sum_k A[m,k] * Bt[bx*128+n, k]  (+resid)
__global__ __launch_bounds__(256)
void gemm_tc(const __nv_bfloat16* __restrict__ Ahi, const __nv_bfloat16* __restrict__ Alo,
             const __nv_bfloat16* __restrict__ Bhi, const __nv_bfloat16* __restrict__ Blo,
             float* __restrict__ C0, float* __restrict__ C1, float* __restrict__ C2,
             int M, const float* __restrict__ resid)
{
    extern __shared__ char smem[];
    const uint32_t sb = smem_to_u32(smem);
    const int tid = threadIdx.x;
    const int wid = tid >> 5;
    const int lane = tid & 31;
    const int warp_m = wid & 1;
    const int warp_n = wid >> 1;
    const int rowBase = blockIdx.y * 128;
    const int mat = blockIdx.x / 3;
    const int colBase = (blockIdx.x % 3) * 128;
    const int btRowBase = blockIdx.x * 128;
    float* C = (mat == 0) ? C0 : (mat == 1 ? C1 : C2);

    float acc[4][4][4];
#pragma unroll
    for (int i = 0; i < 4; i++)
#pragma unroll
        for (int j = 0; j < 4; j++)
#pragma unroll
            for (int l = 0; l < 4; l++) acc[i][j][l] = 0.0f;

    const __nv_bfloat16* srcA[2] = { Ahi, Alo };
    const __nv_bfloat16* srcB[2] = { Bhi, Blo };

    auto load_stage = [&](int buf, int s) {
        const int k0 = s * 32;
#pragma unroll
        for (int i = 0; i < 8; i++) {
            int id = i * 256 + tid;
            int arr = id >> 9;
            int cid = id & 511;
            int row = cid >> 2;
            int c = cid & 3;
            uint32_t dst = sb + buf * STG + arr * ARR + row * PITCH + c * 16;
            const __nv_bfloat16* src;
            bool valid = true;
            if (arr < 2) {
                int gRow = rowBase + row;
                valid = (gRow < M);
                int gr = valid ? gRow : 0;
                src = srcA[arr] + (size_t)gr * DD + k0 + c * 8;
            } else {
                src = srcB[arr - 2] + (size_t)(btRowBase + row) * DD + k0 + c * 8;
            }
            cp16(dst, src, valid);
        }
        asm volatile("cp.async.commit_group;" ::: "memory");
    };

    load_stage(0, 0);

    for (int s = 0; s < 12; s++) {
        asm volatile("cp.async.wait_group 0;" ::: "memory");
        __syncthreads();                         // single barrier per stage
        if (s + 1 < 12) load_stage((s + 1) & 1, s + 1);   // overlaps compute(s)

        const uint32_t st = sb + (s & 1) * STG;
#pragma unroll
        for (int kk = 0; kk < 2; kk++) {
            uint32_t ah[4][4], al[4][4], bh[2][4], bl[2][4];
            const int arow = warp_m * 64;
#pragma unroll
            for (int mt = 0; mt < 4; mt++) {
                uint32_t addr = st + (uint32_t)((arow + mt * 16 + (lane & 15)) * PITCH
                              + kk * 32 + ((lane >> 4) & 1) * 16);
                ldsm_x4(ah[mt], addr);
                ldsm_x4(al[mt], addr + ARR);
            }
#pragma unroll
            for (int p = 0; p < 2; p++) {
                int grp = lane >> 3;
                int row = warp_n * 32 + (p * 2 + (grp >> 1)) * 8 + (lane & 7);
                uint32_t addr = st + 2 * ARR + (uint32_t)(row * PITCH
                              + kk * 32 + (grp & 1) * 16);
                ldsm_x4(bh[p], addr);
                ldsm_x4(bl[p], addr + ARR);
            }
#pragma unroll
            for (int mt = 0; mt < 4; mt++) {
#pragma unroll
                for (int nt = 0; nt < 4; nt++) {
                    const uint32_t* B2h = &bh[nt >> 1][(nt & 1) * 2];
                    const uint32_t* B2l = &bl[nt >> 1][(nt & 1) * 2];
                    mma_bf16(acc[mt][nt], ah[mt], B2h);
                    mma_bf16(acc[mt][nt], ah[mt], B2l);
                    mma_bf16(acc[mt][nt], al[mt], B2h);
                }
            }
        }
    }

#pragma unroll
    for (int mt = 0; mt < 4; mt++) {
        int r0 = rowBase + warp_m * 64 + mt * 16 + (lane >> 2);
#pragma unroll
        for (int nt = 0; nt < 4; nt++) {
            int col = colBase + warp_n * 32 + nt * 8 + (lane & 3) * 2;
#pragma unroll
            for (int half = 0; half < 2; half++) {
                int r = r0 + half * 8;
                if (r >= M) continue;
                size_t off = (size_t)r * DD + col;
                float2 v = make_float2(acc[mt][nt][half * 2], acc[mt][nt][half * 2 + 1]);
                if (resid) {
                    float2 rv = *reinterpret_cast<const float2*>(resid + off);
                    v.x += rv.x; v.y += rv.y;
                }
                *reinterpret_cast<float2*>(C + off) = v;
            }
        }
    }
}

// ---------------- conversions ----------------
__global__ __launch_bounds__(256) void conv_emb(const float* __restrict__ emb) {
    int idx = blockIdx.x * 256 + threadIdx.x;
    if (idx >= NN * DD / 4) return;
    float4 x = reinterpret_cast<const float4*>(emb)[idx];
    __nv_bfloat16 h0 = __float2bfloat16(x.x);
    __nv_bfloat16 h1 = __float2bfloat16(x.y);
    __nv_bfloat16 h2 = __float2bfloat16(x.z);
    __nv_bfloat16 h3 = __float2bfloat16(x.w);
    __nv_bfloat162 hi01, hi23, lo01, lo23;
    hi01.x = h0; hi01.y = h1; hi23.x = h2; hi23.y = h3;
    lo01.x = __float2bfloat16(x.x - __bfloat162float(h0));
    lo01.y = __float2bfloat16(x.y - __bfloat162float(h1));
    lo23.x = __float2bfloat16(x.z - __bfloat162float(h2));
    lo23.y = __float2bfloat16(x.w - __bfloat162float(h3));
    uint2 hiv = make_uint2(*reinterpret_cast<uint32_t*>(&hi01), *reinterpret_cast<uint32_t*>(&hi23));
    uint2 lov = make_uint2(*reinterpret_cast<uint32_t*>(&lo01), *reinterpret_cast<uint32_t*>(&lo23));
    reinterpret_cast<uint2*>(g_emb_hi)[idx] = hiv;
    reinterpret_cast<uint2*>(g_emb_lo)[idx] = lov;
}

__global__ __launch_bounds__(256) void conv_weights(
    const float* __restrict__ WQ, const float* __restrict__ WK,
    const float* __restrict__ WV, const float* __restrict__ WO)
{
    int idx = blockIdx.x * 256 + threadIdx.x;
    if (idx >= 4 * DD * DD) return;
    int mat = idx / (DD * DD);
    int rem = idx - mat * (DD * DD);
    int n = rem / DD;
    int k = rem - n * DD;
    const float* W = (mat == 0) ? WQ : (mat == 1 ? WK : (mat == 2 ? WV : WO));
    float x = W[(size_t)k * DD + n];
    __nv_bfloat16 hi = __float2bfloat16(x);
    __nv_bfloat16 lo = __float2bfloat16(x - __bfloat162float(hi));
    if (mat < 3) {
        size_t o = (size_t)mat * DD * DD + (size_t)n * DD + k;
        g_wt_hi[o] = hi; g_wt_lo[o] = lo;
    } else {
        size_t o = (size_t)n * DD + k;
        g_wo_hi[o] = hi; g_wo_lo[o] = lo;
    }
}

// ---------------- CSR build (side stream) ----------------
__global__ __launch_bounds__(256) void zero_deg() {
    int i = blockIdx.x * 256 + threadIdx.x;
    if (i < NN) g_deg[i] = 0;
}

__global__ __launch_bounds__(256) void hist_kernel(const int* __restrict__ dst) {
    int e = blockIdx.x * 256 + threadIdx.x;
    if (e < EE) atomicAdd(&g_deg[dst[e]], 1);
}

__device__ __forceinline__ int warp_incl_scan(int x, int lane) {
#pragma unroll
    for (int off = 1; off < 32; off <<= 1) {
        int v = __shfl_up_sync(0xffffffffu, x, off);
        if (lane >= off) x += v;
    }
    return x;
}

__global__ __launch_bounds__(1024) void scanA() {
    __shared__ int swarp[32];
    const int tid = threadIdx.x;
    const int w = tid >> 5, lane = tid & 31;
    int idx = blockIdx.x * 1024 + tid;
    int x = (idx < NN) ? g_deg[idx] : 0;
    int incl = warp_incl_scan(x, lane);
    if (lane == 31) swarp[w] = incl;
    __syncthreads();
    if (w == 0) {
        int t = swarp[lane];
        t = warp_incl_scan(t, lane);
        swarp[lane] = t;
    }
    __syncthreads();
    int woff = (w > 0) ? swarp[w - 1] : 0;
    incl += woff;
    if (idx < NN) g_rowptr[idx] = incl;
    if (tid == 1023) g_blocksum[blockIdx.x] = incl;
}

__global__ __launch_bounds__(64) void scanB() {
    __shared__ int sh[64];
    const int tid = threadIdx.x;
    int v = (tid < NSCAN) ? g_blocksum[tid] : 0;
    sh[tid] = v;
    for (int off = 1; off < 64; off <<= 1) {
        __syncthreads();
        int t = (tid >= off) ? sh[tid - off] : 0;
        __syncthreads();
        sh[tid] += t;
    }
    __syncthreads();
    if (tid < NSCAN) g_blocksum[tid] = sh[tid] - v;  // exclusive
    if (tid == 63) g_rowptr[NN] = sh[63];
}

__global__ __launch_bounds__(1024) void scanC() {
    int idx = blockIdx.x * 1024 + threadIdx.x;
    if (idx >= NN) return;
    int ex = g_blocksum[blockIdx.x] + g_rowptr[idx] - g_deg[idx];
    g_rowptr[idx] = ex;
    g_cursor[idx] = ex;
}

__global__ __launch_bounds__(256) void scatter_kernel(
    const int* __restrict__ src, const int* __restrict__ dst,
    const float* __restrict__ eattr)
{
    int e = blockIdx.x * 256 + threadIdx.x;
    if (e >= EE) return;
    int t = dst[e];
    int pos = atomicAdd(&g_cursor[t], 1);
    g_esrc[pos] = src[e];
    g_eea[pos] = eattr[e];
}

// ---------------- fused attention aggregate: warp per node, float4 ----------------
// Each warp handles one node (both heads). float4 index f = lane + 32*j covers 0..95;
// head boundary at element 192 = float4 48 (aligned), so each float4 is single-head.
__global__ __launch_bounds__(256) void node_fused(const float* __restrict__ WE) {
    const int n = blockIdx.x * 8 + (threadIdx.x >> 5);
    if (n >= NN) return;
    const int lane = threadIdx.x & 31;

    float4 qv[3], we4[3];
    bool hd0[3];
    const float4* qrow = reinterpret_cast<const float4*>(g_q + (size_t)n * DD);
    const float4* werow = reinterpret_cast<const float4*>(WE);
#pragma unroll
    for (int j = 0; j < 3; j++) {
        int f = lane + 32 * j;
        qv[j] = qrow[f];
        we4[j] = werow[f];
        hd0[j] = (f < 48);
    }

    // per-head q . WE
    float qe0 = 0.f, qe1 = 0.f;
#pragma unroll
    for (int j = 0; j < 3; j++) {
        float d = qv[j].x * we4[j].x + qv[j].y * we4[j].y
                + qv[j].z * we4[j].z + qv[j].w * we4[j].w;
        if (hd0[j]) qe0 += d; else qe1 += d;
    }
#pragma unroll
    for (int o = 16; o > 0; o >>= 1) {
        qe0 += __shfl_xor_sync(0xffffffffu, qe0, o);
        qe1 += __shfl_xor_sync(0xffffffffu, qe1, o);
    }

    const int beg = g_rowptr[n];
    const int end = g_rowptr[n + 1];

    float m0 = -3.0e38f, m1 = -3.0e38f;
    float den0 = 0.f, den1 = 0.f, sx0 = 0.f, sx1 = 0.f;
    float4 acc[3];
#pragma unroll
    for (int j = 0; j < 3; j++) acc[j] = make_float4(0.f, 0.f, 0.f, 0.f);

    const float SCL = 0.07216878364870323f;  // 1/sqrt(192)

    for (int i = beg; i < end; i++) {
        const int s = g_esrc[i];
        const float ea = g_eea[i];
        const float4* krow = reinterpret_cast<const float4*>(g_k + (size_t)s * DD);
        const float4* vrow = reinterpret_cast<const float4*>(g_v + (size_t)s * DD);

        float4 kv[3], vv[3];
#pragma unroll
        for (int j = 0; j < 3; j++) {
            int f = lane + 32 * j;
            kv[j] = krow[f];
            vv[j] = vrow[f];
        }
        float d0 = 0.f, d1 = 0.f;
#pragma unroll
        for (int j = 0; j < 3; j++) {
            float d = qv[j].x * kv[j].x + qv[j].y * kv[j].y
                    + qv[j].z * kv[j].z + qv[j].w * kv[j].w;
            if (hd0[j]) d0 += d; else d1 += d;
        }
#pragma unroll
        for (int o = 16; o > 0; o >>= 1) {
            d0 += __shfl_xor_sync(0xffffffffu, d0, o);
            d1 += __shfl_xor_sync(0xffffffffu, d1, o);
        }
        float s0 = (d0 + ea * qe0) * SCL;
        float s1 = (d1 + ea * qe1) * SCL;

        float nm0 = fmaxf(m0, s0), nm1 = fmaxf(m1, s1);
        float sc0 = expf(m0 - nm0), sc1 = expf(m1 - nm1);
        float ex0 = expf(s0 - nm0), ex1 = expf(s1 - nm1);
        den0 = den0 * sc0 + ex0;  den1 = den1 * sc1 + ex1;
        sx0 = sx0 * sc0 + ex0 * ea;  sx1 = sx1 * sc1 + ex1 * ea;
#pragma unroll
        for (int j = 0; j < 3; j++) {
            float sc = hd0[j] ? sc0 : sc1;
            float ex = hd0[j] ? ex0 : ex1;
            acc[j].x = acc[j].x * sc + ex * vv[j].x;
            acc[j].y = acc[j].y * sc + ex * vv[j].y;
            acc[j].z = acc[j].z * sc + ex * vv[j].z;
            acc[j].w = acc[j].w * sc + ex * vv[j].w;
        }
        m0 = nm0; m1 = nm1;
    }

    const float inv0 = 1.0f / (den0 + 1e-16f);
    const float inv1 = 1.0f / (den1 + 1e-16f);
    size_t base = (size_t)n * DD;
#pragma unroll
    for (int j = 0; j < 3; j++) {
        int f = lane + 32 * j;
        float sx = hd0[j] ? sx0 : sx1;
        float inv = hd0[j] ? inv0 : inv1;
        float o0 = (acc[j].x + sx * we4[j].x) * inv;
        float o1 = (acc[j].y + sx * we4[j].y) * inv;
        float o2 = (acc[j].z + sx * we4[j].z) * inv;
        float o3 = (acc[j].w + sx * we4[j].w) * inv;
        __nv_bfloat16 h0 = __float2bfloat16(o0);
        __nv_bfloat16 h1 = __float2bfloat16(o1);
        __nv_bfloat16 h2 = __float2bfloat16(o2);
        __nv_bfloat16 h3 = __float2bfloat16(o3);
        __nv_bfloat162 hiA, hiB, loA, loB;
        hiA.x = h0; hiA.y = h1; hiB.x = h2; hiB.y = h3;
        loA.x = __float2bfloat16(o0 - __bfloat162float(h0));
        loA.y = __float2bfloat16(o1 - __bfloat162float(h1));
        loB.x = __float2bfloat16(o2 - __bfloat162float(h2));
        loB.y = __float2bfloat16(o3 - __bfloat162float(h3));
        uint2 hiv = make_uint2(*reinterpret_cast<uint32_t*>(&hiA), *reinterpret_cast<uint32_t*>(&hiB));
        uint2 lov = make_uint2(*reinterpret_cast<uint32_t*>(&loA), *reinterpret_cast<uint32_t*>(&loB));
        *reinterpret_cast<uint2*>(g_agg_hi + base + f * 4) = hiv;
        *reinterpret_cast<uint2*>(g_agg_lo + base + f * 4) = lov;
    }
}

// ---------------- layernorm: warp per row, float4 ----------------
__global__ __launch_bounds__(256) void ln_kernel(
    const float* __restrict__ gw, const float* __restrict__ bw,
    float* __restrict__ out)
{
    const int n = blockIdx.x * 8 + (threadIdx.x >> 5);
    if (n >= NN) return;
    const int lane = threadIdx.x & 31;
    const float4* x = reinterpret_cast<const float4*>(g_tmp + (size_t)n * DD);
    float4 v[3];
    float su = 0.f, sq = 0.f;
#pragma unroll
    for (int j = 0; j < 3; j++) {
        v[j] = x[lane + 32 * j];
        su += v[j].x + v[j].y + v[j].z + v[j].w;
        sq += v[j].x * v[j].x + v[j].y * v[j].y + v[j].z * v[j].z + v[j].w * v[j].w;
    }
#pragma unroll
    for (int o = 16; o > 0; o >>= 1) {
        su += __shfl_xor_sync(0xffffffffu, su, o);
        sq += __shfl_xor_sync(0xffffffffu, sq, o);
    }
    float mu = su * (1.0f / DD);
    float var = sq * (1.0f / DD) - mu * mu;
    float inv = rsqrtf(var + 1e-5f);
    const float4* g4 = reinterpret_cast<const float4*>(gw);
    const float4* b4 = reinterpret_cast<const float4*>(bw);
    float4* o4 = reinterpret_cast<float4*>(out + (size_t)n * DD);
#pragma unroll
    for (int j = 0; j < 3; j++) {
        float4 g = g4[lane + 32 * j];
        float4 b = b4[lane + 32 * j];
        float4 r;
        r.x = (v[j].x - mu) * inv * g.x + b.x;
        r.y = (v[j].y - mu) * inv * g.y + b.y;
        r.z = (v[j].z - mu) * inv * g.z + b.z;
        r.w = (v[j].w - mu) * inv * g.w + b.w;
        o4[lane + 32 * j] = r;
    }
}

// ---------------- launch ----------------
extern "C" void kernel_launch(void* const* d_in, const int* in_sizes, int n_in,
                              void* d_out, int out_size)
{
    const float* emb   = (const float*)d_in[0];
    const int*   eidx  = (const int*)  d_in[1];
    const float* eattr = (const float*)d_in[2];
    const float* WQ    = (const float*)d_in[3];
    const float* WK    = (const float*)d_in[4];
    const float* WV    = (const float*)d_in[5];
    const float* WE    = (const float*)d_in[6];
    const float* WO    = (const float*)d_in[7];
    const float* ln_g  = (const float*)d_in[8];
    const float* ln_b  = (const float*)d_in[9];
    float* out = (float*)d_out;

    const int* src = eidx;
    const int* dst = eidx + EE;

    static bool inited = false;
    static cudaStream_t s_side;
    static cudaEvent_t ev_fork, ev_join, ev_w;
    if (!inited) {
        cudaFuncSetAttribute(gemm_tc, cudaFuncAttributeMaxDynamicSharedMemorySize, SM_TOTAL);
        cudaStreamCreateWithFlags(&s_side, cudaStreamNonBlocking);
        cudaEventCreateWithFlags(&ev_fork, cudaEventDisableTiming);
        cudaEventCreateWithFlags(&ev_join, cudaEventDisableTiming);
        cudaEventCreateWithFlags(&ev_w, cudaEventDisableTiming);
        inited = true;
    }

    float *dq, *dk, *dv, *dtmp;
    __nv_bfloat16 *dembh, *dembl, *daggh, *daggl, *dwth, *dwtl, *dwoh, *dwol;
    cudaGetSymbolAddress((void**)&dq,    g_q);
    cudaGetSymbolAddress((void**)&dk,    g_k);
    cudaGetSymbolAddress((void**)&dv,    g_v);
    cudaGetSymbolAddress((void**)&dtmp,  g_tmp);
    cudaGetSymbolAddress((void**)&dembh, g_emb_hi);
    cudaGetSymbolAddress((void**)&dembl, g_emb_lo);
    cudaGetSymbolAddress((void**)&daggh, g_agg_hi);
    cudaGetSymbolAddress((void**)&daggl, g_agg_lo);
    cudaGetSymbolAddress((void**)&dwth,  g_wt_hi);
    cudaGetSymbolAddress((void**)&dwtl,  g_wt_lo);
    cudaGetSymbolAddress((void**)&dwoh,  g_wo_hi);
    cudaGetSymbolAddress((void**)&dwol,  g_wo_lo);

    // ---- fork: weights conversion + CSR build on side stream ----
    cudaEventRecord(ev_fork, 0);
    cudaStreamWaitEvent(s_side, ev_fork, 0);
    conv_weights<<<(4 * DD * DD + 255) / 256, 256, 0, s_side>>>(WQ, WK, WV, WO);
    cudaEventRecord(ev_w, s_side);
    zero_deg<<<(NN + 255) / 256, 256, 0, s_side>>>();
    hist_kernel<<<(EE + 255) / 256, 256, 0, s_side>>>(dst);
    scanA<<<NSCAN, 1024, 0, s_side>>>();
    scanB<<<1, 64, 0, s_side>>>();
    scanC<<<NSCAN, 1024, 0, s_side>>>();
    scatter_kernel<<<(EE + 255) / 256, 256, 0, s_side>>>(src, dst, eattr);
    cudaEventRecord(ev_join, s_side);

    // ---- main stream: emb conversion + QKV projections ----
    conv_emb<<<(NN * DD / 4 + 255) / 256, 256>>>(emb);
    cudaStreamWaitEvent(0, ev_w, 0);

    const int MT = (NN + 127) / 128;
    gemm_tc<<<dim3(9, MT), 256, SM_TOTAL>>>(dembh, dembl, dwth, dwtl,
                                            dq, dk, dv, NN, nullptr);

    // ---- join, then fused attention ----
    cudaStreamWaitEvent(0, ev_join, 0);
    node_fused<<<(NN + 7) / 8, 256>>>(WE);

    // output projection + residual
    gemm_tc<<<dim3(3, MT), 256, SM_TOTAL>>>(daggh, daggl, dwoh, dwol,
                                            dtmp, dtmp, dtmp, NN, emb);

    // layernorm -> out
    ln_kernel<<<(NN + 7) / 8, 256>>>(ln_g, ln_b, out);
}

// round 10
// speedup vs baseline: 1.1589x; 1.0176x over previous
#include <cuda_runtime.h>
#include <cuda_bf16.h>
#include <math.h>
#include <stdint.h>

// Problem constants (fixed by the reference)
#define NN 50000
#define EE 200000
#define DD 384
#define HH 2
#define DHH 192

#define SCAN_BLK 1024
#define NSCAN ((NN + SCAN_BLK - 1) / SCAN_BLK)   // 49

// ---------------- device scratch (allocation-free requirement) ----------------
__device__ float g_q[(size_t)NN * DD];
__device__ float g_k[(size_t)NN * DD];
__device__ float g_v[(size_t)NN * DD];
__device__ float g_tmp[(size_t)NN * DD];

__device__ int   g_deg[NN];
__device__ int   g_rowptr[NN + 1];
__device__ int   g_cursor[NN];
__device__ int   g_blocksum[NSCAN];
__device__ int   g_esrc[EE];
__device__ float g_eea[EE];

__device__ __nv_bfloat16 g_emb_hi[(size_t)NN * DD];
__device__ __nv_bfloat16 g_emb_lo[(size_t)NN * DD];
__device__ __nv_bfloat16 g_agg_hi[(size_t)NN * DD];
__device__ __nv_bfloat16 g_agg_lo[(size_t)NN * DD];
__device__ __nv_bfloat16 g_wt_hi[(size_t)3 * DD * DD];   // [WQ|WK|WV]^T  [1152(N), 384(K)]
__device__ __nv_bfloat16 g_wt_lo[(size_t)3 * DD * DD];
__device__ __nv_bfloat16 g_wo_hi[(size_t)DD * DD];       // WO^T [384, 384]
__device__ __nv_bfloat16 g_wo_lo[(size_t)DD * DD];

// ---------------- PTX helpers (baseline features only; PTX target is compute_103) ----------------
__device__ __forceinline__ uint32_t smem_to_u32(const void* p) {
    uint32_t a;
    asm("{ .reg .u64 t; cvta.to.shared.u64 t, %1; cvt.u32.u64 %0, t; }" : "=r"(a) : "l"(p));
    return a;
}
__device__ __forceinline__ void ldsm_x4(uint32_t* r, uint32_t addr) {
    asm volatile("ldmatrix.sync.aligned.m8n8.x4.shared.b16 {%0,%1,%2,%3}, [%4];"
        : "=r"(r[0]), "=r"(r[1]), "=r"(r[2]), "=r"(r[3]) : "r"(addr));
}
__device__ __forceinline__ void mma_bf16(float* c, const uint32_t* a, const uint32_t* b) {
    asm volatile(
        "mma.sync.aligned.m16n8k16.row.col.f32.bf16.bf16.f32 "
        "{%0,%1,%2,%3}, {%4,%5,%6,%7}, {%8,%9}, {%0,%1,%2,%3};"
        : "+f"(c[0]), "+f"(c[1]), "+f"(c[2]), "+f"(c[3])
        : "r"(a[0]), "r"(a[1]), "r"(a[2]), "r"(a[3]), "r"(b[0]), "r"(b[1]));
}
__device__ __forceinline__ void cp16(uint32_t dst, const void* src, bool valid) {
    int sz = valid ? 16 : 0;
    asm volatile("cp.async.cg.shared.global [%0], [%1], 16, %2;"
        :: "r"(dst), "l"(src), "r"(sz) : "memory");
}

// smem geometry: 4 operand arrays (Ahi,Alo,Bhi,Blo), 128 rows x 80B pitch, double-buffered
// 80 KB/CTA -> 2 CTAs/SM (R7 config, measured best: 646.6us)
#define PITCH 80
#define ARR   10240          // 128 * 80
#define STG   40960          // 4 * ARR
#define SM_TOTAL (2 * STG)   // 81920

// ---------------- bf16x3 HMMA GEMM ----------------
// C[m, colBase+n] = sum_k A[m,k] * Bt[bx*128+n, k]  (+resid)
__global__ __launch_bounds__(256)
void gemm_tc(const __nv_bfloat16* __restrict__ Ahi, const __nv_bfloat16* __restrict__ Alo,
             const __nv_bfloat16* __restrict__ Bhi, const __nv_bfloat16* __restrict__ Blo,
             float* __restrict__ C0, float* __restrict__ C1, float* __restrict__ C2,
             int M, const float* __restrict__ resid)
{
    extern __shared__ char smem[];
    const uint32_t sb = smem_to_u32(smem);
    const int tid = threadIdx.x;
    const int wid = tid >> 5;
    const int lane = tid & 31;
    const int warp_m = wid & 1;
    const int warp_n = wid >> 1;
    const int rowBase = blockIdx.y * 128;
    const int mat = blockIdx.x / 3;
    const int colBase = (blockIdx.x % 3) * 128;
    const int btRowBase = blockIdx.x * 128;
    float* C = (mat == 0) ? C0 : (mat == 1 ? C1 : C2);

    float acc[4][4][4];
#pragma unroll
    for (int i = 0; i < 4; i++)
#pragma unroll
        for (int j = 0; j < 4; j++)
#pragma unroll
            for (int l = 0; l < 4; l++) acc[i][j][l] = 0.0f;

    const __nv_bfloat16* srcA[2] = { Ahi, Alo };
    const __nv_bfloat16* srcB[2] = { Bhi, Blo };

    auto load_stage = [&](int buf, int s) {
        const int k0 = s * 32;
#pragma unroll
        for (int i = 0; i < 8; i++) {
            int id = i * 256 + tid;
            int arr = id >> 9;
            int cid = id & 511;
            int row = cid >> 2;
            int c = cid & 3;
            uint32_t dst = sb + buf * STG + arr * ARR + row * PITCH + c * 16;
            const __nv_bfloat16* src;
            bool valid = true;
            if (arr < 2) {
                int gRow = rowBase + row;
                valid = (gRow < M);
                int gr = valid ? gRow : 0;
                src = srcA[arr] + (size_t)gr * DD + k0 + c * 8;
            } else {
                src = srcB[arr - 2] + (size_t)(btRowBase + row) * DD + k0 + c * 8;
            }
            cp16(dst, src, valid);
        }
        asm volatile("cp.async.commit_group;" ::: "memory");
    };

    load_stage(0, 0);

    for (int s = 0; s < 12; s++) {
        asm volatile("cp.async.wait_group 0;" ::: "memory");
        __syncthreads();                         // single barrier per stage
        if (s + 1 < 12) load_stage((s + 1) & 1, s + 1);   // overlaps compute(s)

        const uint32_t st = sb + (s & 1) * STG;
#pragma unroll
        for (int kk = 0; kk < 2; kk++) {
            uint32_t ah[4][4], al[4][4], bh[2][4], bl[2][4];
            const int arow = warp_m * 64;
#pragma unroll
            for (int mt = 0; mt < 4; mt++) {
                uint32_t addr = st + (uint32_t)((arow + mt * 16 + (lane & 15)) * PITCH
                              + kk * 32 + ((lane >> 4) & 1) * 16);
                ldsm_x4(ah[mt], addr);
                ldsm_x4(al[mt], addr + ARR);
            }
#pragma unroll
            for (int p = 0; p < 2; p++) {
                int grp = lane >> 3;
                int row = warp_n * 32 + (p * 2 + (grp >> 1)) * 8 + (lane & 7);
                uint32_t addr = st + 2 * ARR + (uint32_t)(row * PITCH
                              + kk * 32 + (grp & 1) * 16);
                ldsm_x4(bh[p], addr);
                ldsm_x4(bl[p], addr + ARR);
            }
#pragma unroll
            for (int mt = 0; mt < 4; mt++) {
#pragma unroll
                for (int nt = 0; nt < 4; nt++) {
                    const uint32_t* B2h = &bh[nt >> 1][(nt & 1) * 2];
                    const uint32_t* B2l = &bl[nt >> 1][(nt & 1) * 2];
                    mma_bf16(acc[mt][nt], ah[mt], B2h);
                    mma_bf16(acc[mt][nt], ah[mt], B2l);
                    mma_bf16(acc[mt][nt], al[mt], B2h);
                }
            }
        }
    }

#pragma unroll
    for (int mt = 0; mt < 4; mt++) {
        int r0 = rowBase + warp_m * 64 + mt * 16 + (lane >> 2);
#pragma unroll
        for (int nt = 0; nt < 4; nt++) {
            int col = colBase + warp_n * 32 + nt * 8 + (lane & 3) * 2;
#pragma unroll
            for (int half = 0; half < 2; half++) {
                int r = r0 + half * 8;
                if (r >= M) continue;
                size_t off = (size_t)r * DD + col;
                float2 v = make_float2(acc[mt][nt][half * 2], acc[mt][nt][half * 2 + 1]);
                if (resid) {
                    float2 rv = *reinterpret_cast<const float2*>(resid + off);
                    v.x += rv.x; v.y += rv.y;
                }
                *reinterpret_cast<float2*>(C + off) = v;
            }
        }
    }
}

// ---------------- conversions ----------------
__global__ __launch_bounds__(256) void conv_emb(const float* __restrict__ emb) {
    int idx = blockIdx.x * 256 + threadIdx.x;
    if (idx >= NN * DD / 4) return;
    float4 x = reinterpret_cast<const float4*>(emb)[idx];
    __nv_bfloat16 h0 = __float2bfloat16(x.x);
    __nv_bfloat16 h1 = __float2bfloat16(x.y);
    __nv_bfloat16 h2 = __float2bfloat16(x.z);
    __nv_bfloat16 h3 = __float2bfloat16(x.w);
    __nv_bfloat162 hi01, hi23, lo01, lo23;
    hi01.x = h0; hi01.y = h1; hi23.x = h2; hi23.y = h3;
    lo01.x = __float2bfloat16(x.x - __bfloat162float(h0));
    lo01.y = __float2bfloat16(x.y - __bfloat162float(h1));
    lo23.x = __float2bfloat16(x.z - __bfloat162float(h2));
    lo23.y = __float2bfloat16(x.w - __bfloat162float(h3));
    uint2 hiv = make_uint2(*reinterpret_cast<uint32_t*>(&hi01), *reinterpret_cast<uint32_t*>(&hi23));
    uint2 lov = make_uint2(*reinterpret_cast<uint32_t*>(&lo01), *reinterpret_cast<uint32_t*>(&lo23));
    reinterpret_cast<uint2*>(g_emb_hi)[idx] = hiv;
    reinterpret_cast<uint2*>(g_emb_lo)[idx] = lov;
}

// weights transpose/split; also zeroes the degree histogram (runs first on the side stream)
__global__ __launch_bounds__(256) void conv_weights(
    const float* __restrict__ WQ, const float* __restrict__ WK,
    const float* __restrict__ WV, const float* __restrict__ WO)
{
    int idx = blockIdx.x * 256 + threadIdx.x;
    if (idx < NN) g_deg[idx] = 0;
    if (idx >= 4 * DD * DD) return;
    int mat = idx / (DD * DD);
    int rem = idx - mat * (DD * DD);
    int n = rem / DD;
    int k = rem - n * DD;
    const float* W = (mat == 0) ? WQ : (mat == 1 ? WK : (mat == 2 ? WV : WO));
    float x = W[(size_t)k * DD + n];
    __nv_bfloat16 hi = __float2bfloat16(x);
    __nv_bfloat16 lo = __float2bfloat16(x - __bfloat162float(hi));
    if (mat < 3) {
        size_t o = (size_t)mat * DD * DD + (size_t)n * DD + k;
        g_wt_hi[o] = hi; g_wt_lo[o] = lo;
    } else {
        size_t o = (size_t)n * DD + k;
        g_wo_hi[o] = hi; g_wo_lo[o] = lo;
    }
}

// ---------------- CSR build (side stream) ----------------
__global__ __launch_bounds__(256) void hist_kernel(const int* __restrict__ dst) {
    int e = blockIdx.x * 256 + threadIdx.x;
    if (e < EE) atomicAdd(&g_deg[dst[e]], 1);
}

__device__ __forceinline__ int warp_incl_scan(int x, int lane) {
#pragma unroll
    for (int off = 1; off < 32; off <<= 1) {
        int v = __shfl_up_sync(0xffffffffu, x, off);
        if (lane >= off) x += v;
    }
    return x;
}

__global__ __launch_bounds__(1024) void scanA() {
    __shared__ int swarp[32];
    const int tid = threadIdx.x;
    const int w = tid >> 5, lane = tid & 31;
    int idx = blockIdx.x * 1024 + tid;
    int x = (idx < NN) ? g_deg[idx] : 0;
    int incl = warp_incl_scan(x, lane);
    if (lane == 31) swarp[w] = incl;
    __syncthreads();
    if (w == 0) {
        int t = swarp[lane];
        t = warp_incl_scan(t, lane);
        swarp[lane] = t;
    }
    __syncthreads();
    int woff = (w > 0) ? swarp[w - 1] : 0;
    incl += woff;
    if (idx < NN) g_rowptr[idx] = incl;
    if (tid == 1023) g_blocksum[blockIdx.x] = incl;
}

__global__ __launch_bounds__(64) void scanB() {
    __shared__ int sh[64];
    const int tid = threadIdx.x;
    int v = (tid < NSCAN) ? g_blocksum[tid] : 0;
    sh[tid] = v;
    for (int off = 1; off < 64; off <<= 1) {
        __syncthreads();
        int t = (tid >= off) ? sh[tid - off] : 0;
        __syncthreads();
        sh[tid] += t;
    }
    __syncthreads();
    if (tid < NSCAN) g_blocksum[tid] = sh[tid] - v;  // exclusive
    if (tid == 63) g_rowptr[NN] = sh[63];
}

__global__ __launch_bounds__(1024) void scanC() {
    int idx = blockIdx.x * 1024 + threadIdx.x;
    if (idx >= NN) return;
    int ex = g_blocksum[blockIdx.x] + g_rowptr[idx] - g_deg[idx];
    g_rowptr[idx] = ex;
    g_cursor[idx] = ex;
}

__global__ __launch_bounds__(256) void scatter_kernel(
    const int* __restrict__ src, const int* __restrict__ dst,
    const float* __restrict__ eattr)
{
    int e = blockIdx.x * 256 + threadIdx.x;
    if (e >= EE) return;
    int t = dst[e];
    int pos = atomicAdd(&g_cursor[t], 1);
    g_esrc[pos] = src[e];
    g_eea[pos] = eattr[e];
}

// ---------------- fused attention aggregate: warp per (node, head) ----------------
__global__ __launch_bounds__(256) void node_fused(const float* __restrict__ WE) {
    const int gw = blockIdx.x * 8 + (threadIdx.x >> 5);
    const int n = gw >> 1;
    if (n >= NN) return;
    const int h = gw & 1;
    const int hb = h * DHH;
    const int lane = threadIdx.x & 31;

    float qv[6], we[6];
    const float* qrow = g_q + (size_t)n * DD + hb;
    const float* werow = WE + hb;
#pragma unroll
    for (int j = 0; j < 6; j++) {
        int d = lane + 32 * j;
        qv[j] = qrow[d];
        we[j] = werow[d];
    }

    // qe = q_h . WE_h
    float qe = 0.f;
#pragma unroll
    for (int j = 0; j < 6; j++) qe += qv[j] * we[j];
#pragma unroll
    for (int o = 16; o > 0; o >>= 1) qe += __shfl_xor_sync(0xffffffffu, qe, o);

    const int beg = g_rowptr[n];
    const int end = g_rowptr[n + 1];

    float m0 = -3.0e38f, den = 0.f, sexa = 0.f;
    float acc[6];
#pragma unroll
    for (int j = 0; j < 6; j++) acc[j] = 0.f;

    const float SCL = 0.07216878364870323f;  // 1/sqrt(192)

    for (int i = beg; i < end; i++) {
        const int s = g_esrc[i];
        const float ea = g_eea[i];
        const float* krow = g_k + (size_t)s * DD + hb;
        const float* vrow = g_v + (size_t)s * DD + hb;

        float kv[6], vv[6];
#pragma unroll
        for (int j = 0; j < 6; j++) {
            int d = lane + 32 * j;
            kv[j] = krow[d];
            vv[j] = vrow[d];
        }
        float ds = 0.f;
#pragma unroll
        for (int j = 0; j < 6; j++) ds += qv[j] * kv[j];
#pragma unroll
        for (int o = 16; o > 0; o >>= 1) ds += __shfl_xor_sync(0xffffffffu, ds, o);
        float s0 = (ds + ea * qe) * SCL;

        float nm = fmaxf(m0, s0);
        float sc = __expf(m0 - nm);
        float ex = __expf(s0 - nm);
        den = den * sc + ex;
        sexa = sexa * sc + ex * ea;
#pragma unroll
        for (int j = 0; j < 6; j++) acc[j] = acc[j] * sc + ex * vv[j];
        m0 = nm;
    }

    const float inv = 1.0f / (den + 1e-16f);
    size_t base = (size_t)n * DD + hb;
#pragma unroll
    for (int j = 0; j < 6; j++) {
        int d = lane + 32 * j;
        float o0 = (acc[j] + sexa * we[j]) * inv;
        __nv_bfloat16 hi = __float2bfloat16(o0);
        g_agg_hi[base + d] = hi;
        g_agg_lo[base + d] = __float2bfloat16(o0 - __bfloat162float(hi));
    }
}

// ---------------- layernorm: warp per row, float4 ----------------
__global__ __launch_bounds__(256) void ln_kernel(
    const float* __restrict__ gw, const float* __restrict__ bw,
    float* __restrict__ out)
{
    const int n = blockIdx.x * 8 + (threadIdx.x >> 5);
    if (n >= NN) return;
    const int lane = threadIdx.x & 31;
    const float4* x = reinterpret_cast<const float4*>(g_tmp + (size_t)n * DD);
    float4 v[3];
    float su = 0.f, sq = 0.f;
#pragma unroll
    for (int j = 0; j < 3; j++) {
        v[j] = x[lane + 32 * j];
        su += v[j].x + v[j].y + v[j].z + v[j].w;
        sq += v[j].x * v[j].x + v[j].y * v[j].y + v[j].z * v[j].z + v[j].w * v[j].w;
    }
#pragma unroll
    for (int o = 16; o > 0; o >>= 1) {
        su += __shfl_xor_sync(0xffffffffu, su, o);
        sq += __shfl_xor_sync(0xffffffffu, sq, o);
    }
    float mu = su * (1.0f / DD);
    float var = sq * (1.0f / DD) - mu * mu;
    float inv = rsqrtf(var + 1e-5f);
    const float4* g4 = reinterpret_cast<const float4*>(gw);
    const float4* b4 = reinterpret_cast<const float4*>(bw);
    float4* o4 = reinterpret_cast<float4*>(out + (size_t)n * DD);
#pragma unroll
    for (int j = 0; j < 3; j++) {
        float4 g = g4[lane + 32 * j];
        float4 b = b4[lane + 32 * j];
        float4 r;
        r.x = (v[j].x - mu) * inv * g.x + b.x;
        r.y = (v[j].y - mu) * inv * g.y + b.y;
        r.z = (v[j].z - mu) * inv * g.z + b.z;
        r.w = (v[j].w - mu) * inv * g.w + b.w;
        o4[lane + 32 * j] = r;
    }
}

// ---------------- launch ----------------
extern "C" void kernel_launch(void* const* d_in, const int* in_sizes, int n_in,
                              void* d_out, int out_size)
{
    const float* emb   = (const float*)d_in[0];
    const int*   eidx  = (const int*)  d_in[1];
    const float* eattr = (const float*)d_in[2];
    const float* WQ    = (const float*)d_in[3];
    const float* WK    = (const float*)d_in[4];
    const float* WV    = (const float*)d_in[5];
    const float* WE    = (const float*)d_in[6];
    const float* WO    = (const float*)d_in[7];
    const float* ln_g  = (const float*)d_in[8];
    const float* ln_b  = (const float*)d_in[9];
    float* out = (float*)d_out;

    const int* src = eidx;
    const int* dst = eidx + EE;

    static bool inited = false;
    static cudaStream_t s_side;
    static cudaEvent_t ev_fork, ev_join, ev_w;
    if (!inited) {
        cudaFuncSetAttribute(gemm_tc, cudaFuncAttributeMaxDynamicSharedMemorySize, SM_TOTAL);
        cudaStreamCreateWithFlags(&s_side, cudaStreamNonBlocking);
        cudaEventCreateWithFlags(&ev_fork, cudaEventDisableTiming);
        cudaEventCreateWithFlags(&ev_join, cudaEventDisableTiming);
        cudaEventCreateWithFlags(&ev_w, cudaEventDisableTiming);
        inited = true;
    }

    float *dq, *dk, *dv, *dtmp;
    __nv_bfloat16 *dembh, *dembl, *daggh, *daggl, *dwth, *dwtl, *dwoh, *dwol;
    cudaGetSymbolAddress((void**)&dq,    g_q);
    cudaGetSymbolAddress((void**)&dk,    g_k);
    cudaGetSymbolAddress((void**)&dv,    g_v);
    cudaGetSymbolAddress((void**)&dtmp,  g_tmp);
    cudaGetSymbolAddress((void**)&dembh, g_emb_hi);
    cudaGetSymbolAddress((void**)&dembl, g_emb_lo);
    cudaGetSymbolAddress((void**)&daggh, g_agg_hi);
    cudaGetSymbolAddress((void**)&daggl, g_agg_lo);
    cudaGetSymbolAddress((void**)&dwth,  g_wt_hi);
    cudaGetSymbolAddress((void**)&dwtl,  g_wt_lo);
    cudaGetSymbolAddress((void**)&dwoh,  g_wo_hi);
    cudaGetSymbolAddress((void**)&dwol,  g_wo_lo);

    // ---- fork: weights conversion (+deg zeroing) + CSR build on side stream ----
    cudaEventRecord(ev_fork, 0);
    cudaStreamWaitEvent(s_side, ev_fork, 0);
    conv_weights<<<(4 * DD * DD + 255) / 256, 256, 0, s_side>>>(WQ, WK, WV, WO);
    cudaEventRecord(ev_w, s_side);
    hist_kernel<<<(EE + 255) / 256, 256, 0, s_side>>>(dst);
    scanA<<<NSCAN, 1024, 0, s_side>>>();
    scanB<<<1, 64, 0, s_side>>>();
    scanC<<<NSCAN, 1024, 0, s_side>>>();
    scatter_kernel<<<(EE + 255) / 256, 256, 0, s_side>>>(src, dst, eattr);
    cudaEventRecord(ev_join, s_side);

    // ---- main stream: emb conversion + QKV projections ----
    conv_emb<<<(NN * DD / 4 + 255) / 256, 256>>>(emb);
    cudaStreamWaitEvent(0, ev_w, 0);

    const int MT = (NN + 127) / 128;
    gemm_tc<<<dim3(9, MT), 256, SM_TOTAL>>>(dembh, dembl, dwth, dwtl,
                                            dq, dk, dv, NN, nullptr);

    // ---- join, then fused attention ----
    cudaStreamWaitEvent(0, ev_join, 0);
    node_fused<<<(2 * NN + 7) / 8, 256>>>(WE);

    // output projection + residual
    gemm_tc<<<dim3(3, MT), 256, SM_TOTAL>>>(daggh, daggl, dwoh, dwol,
                                            dtmp, dtmp, dtmp, NN, emb);

    // layernorm -> out
    ln_kernel<<<(NN + 7) / 8, 256>>>(ln_g, ln_b, out);
}

// round 11
// speedup vs baseline: 1.1617x; 1.0025x over previous
#include <cuda_runtime.h>
#include <cuda_bf16.h>
#include <math.h>
#include <stdint.h>

// Problem constants (fixed by the reference)
#define NN 50000
#define EE 200000
#define DD 384
#define HH 2
#define DHH 192

#define SCAN_BLK 1024
#define NSCAN ((NN + SCAN_BLK - 1) / SCAN_BLK)   // 49

// ---------------- device scratch (allocation-free requirement) ----------------
__device__ float g_q[(size_t)NN * DD];
__device__ float g_k[(size_t)NN * DD];
__device__ float g_v[(size_t)NN * DD];
__device__ float g_tmp[(size_t)NN * DD];

__device__ int   g_deg[NN];
__device__ int   g_rowptr[NN + 1];
__device__ int   g_cursor[NN];
__device__ int   g_blocksum[NSCAN];
__device__ int   g_esrc[EE];
__device__ float g_eea[EE];

__device__ __nv_bfloat16 g_emb_hi[(size_t)NN * DD];
__device__ __nv_bfloat16 g_emb_lo[(size_t)NN * DD];
__device__ __nv_bfloat16 g_agg_hi[(size_t)NN * DD];
__device__ __nv_bfloat16 g_agg_lo[(size_t)NN * DD];
__device__ __nv_bfloat16 g_wt_hi[(size_t)3 * DD * DD];   // [WQ|WK|WV]^T  [1152(N), 384(K)]
__device__ __nv_bfloat16 g_wt_lo[(size_t)3 * DD * DD];
__device__ __nv_bfloat16 g_wo_hi[(size_t)DD * DD];       // WO^T [384, 384]
__device__ __nv_bfloat16 g_wo_lo[(size_t)DD * DD];

// ---------------- PTX helpers (baseline features only; PTX target is compute_103) ----------------
__device__ __forceinline__ uint32_t smem_to_u32(const void* p) {
    uint32_t a;
    asm("{ .reg .u64 t; cvta.to.shared.u64 t, %1; cvt.u32.u64 %0, t; }" : "=r"(a) : "l"(p));
    return a;
}
__device__ __forceinline__ void ldsm_x4(uint32_t* r, uint32_t addr) {
    asm volatile("ldmatrix.sync.aligned.m8n8.x4.shared.b16 {%0,%1,%2,%3}, [%4];"
        : "=r"(r[0]), "=r"(r[1]), "=r"(r[2]), "=r"(r[3]) : "r"(addr));
}
__device__ __forceinline__ void mma_bf16(float* c, const uint32_t* a, const uint32_t* b) {
    asm volatile(
        "mma.sync.aligned.m16n8k16.row.col.f32.bf16.bf16.f32 "
        "{%0,%1,%2,%3}, {%4,%5,%6,%7}, {%8,%9}, {%0,%1,%2,%3};"
        : "+f"(c[0]), "+f"(c[1]), "+f"(c[2]), "+f"(c[3])
        : "r"(a[0]), "r"(a[1]), "r"(a[2]), "r"(a[3]), "r"(b[0]), "r"(b[1]));
}
__device__ __forceinline__ void cp16(uint32_t dst, const void* src, bool valid) {
    int sz = valid ? 16 : 0;
    asm volatile("cp.async.cg.shared.global [%0], [%1], 16, %2;"
        :: "r"(dst), "l"(src), "r"(sz) : "memory");
}

// smem geometry: 4 operand arrays (Ahi,Alo,Bhi,Blo), 128 rows x 80B pitch, double-buffered
// 80 KB/CTA -> 2 CTAs/SM (R7 config, measured best: 646.6us)
#define PITCH 80
#define ARR   10240          // 128 * 80
#define STG   40960          // 4 * ARR
#define SM_TOTAL (2 * STG)   // 81920

// ---------------- bf16x3 HMMA GEMM ----------------
// C[m, colBase+n] = sum_k A[m,k] * Bt[bx*128+n, k]  (+resid)
__global__ __launch_bounds__(256)
void gemm_tc(const __nv_bfloat16* __restrict__ Ahi, const __nv_bfloat16* __restrict__ Alo,
             const __nv_bfloat16* __restrict__ Bhi, const __nv_bfloat16* __restrict__ Blo,
             float* __restrict__ C0, float* __restrict__ C1, float* __restrict__ C2,
             int M, const float* __restrict__ resid)
{
    extern __shared__ char smem[];
    const uint32_t sb = smem_to_u32(smem);
    const int tid = threadIdx.x;
    const int wid = tid >> 5;
    const int lane = tid & 31;
    const int warp_m = wid & 1;
    const int warp_n = wid >> 1;
    const int rowBase = blockIdx.y * 128;
    const int mat = blockIdx.x / 3;
    const int colBase = (blockIdx.x % 3) * 128;
    const int btRowBase = blockIdx.x * 128;
    float* C = (mat == 0) ? C0 : (mat == 1 ? C1 : C2);

    float acc[4][4][4];
#pragma unroll
    for (int i = 0; i < 4; i++)
#pragma unroll
        for (int j = 0; j < 4; j++)
#pragma unroll
            for (int l = 0; l < 4; l++) acc[i][j][l] = 0.0f;

    const __nv_bfloat16* srcA[2] = { Ahi, Alo };
    const __nv_bfloat16* srcB[2] = { Bhi, Blo };

    auto load_stage = [&](int buf, int s) {
        const int k0 = s * 32;
#pragma unroll
        for (int i = 0; i < 8; i++) {
            int id = i * 256 + tid;
            int arr = id >> 9;
            int cid = id & 511;
            int row = cid >> 2;
            int c = cid & 3;
            uint32_t dst = sb + buf * STG + arr * ARR + row * PITCH + c * 16;
            const __nv_bfloat16* src;
            bool valid = true;
            if (arr < 2) {
                int gRow = rowBase + row;
                valid = (gRow < M);
                int gr = valid ? gRow : 0;
                src = srcA[arr] + (size_t)gr * DD + k0 + c * 8;
            } else {
                src = srcB[arr - 2] + (size_t)(btRowBase + row) * DD + k0 + c * 8;
            }
            cp16(dst, src, valid);
        }
        asm volatile("cp.async.commit_group;" ::: "memory");
    };

    load_stage(0, 0);

    for (int s = 0; s < 12; s++) {
        asm volatile("cp.async.wait_group 0;" ::: "memory");
        __syncthreads();                         // single barrier per stage
        if (s + 1 < 12) load_stage((s + 1) & 1, s + 1);   // overlaps compute(s)

        const uint32_t st = sb + (s & 1) * STG;
#pragma unroll
        for (int kk = 0; kk < 2; kk++) {
            uint32_t ah[4][4], al[4][4], bh[2][4], bl[2][4];
            const int arow = warp_m * 64;
#pragma unroll
            for (int mt = 0; mt < 4; mt++) {
                uint32_t addr = st + (uint32_t)((arow + mt * 16 + (lane & 15)) * PITCH
                              + kk * 32 + ((lane >> 4) & 1) * 16);
                ldsm_x4(ah[mt], addr);
                ldsm_x4(al[mt], addr + ARR);
            }
#pragma unroll
            for (int p = 0; p < 2; p++) {
                int grp = lane >> 3;
                int row = warp_n * 32 + (p * 2 + (grp >> 1)) * 8 + (lane & 7);
                uint32_t addr = st + 2 * ARR + (uint32_t)(row * PITCH
                              + kk * 32 + (grp & 1) * 16);
                ldsm_x4(bh[p], addr);
                ldsm_x4(bl[p], addr + ARR);
            }
#pragma unroll
            for (int mt = 0; mt < 4; mt++) {
#pragma unroll
                for (int nt = 0; nt < 4; nt++) {
                    const uint32_t* B2h = &bh[nt >> 1][(nt & 1) * 2];
                    const uint32_t* B2l = &bl[nt >> 1][(nt & 1) * 2];
                    mma_bf16(acc[mt][nt], ah[mt], B2h);
                    mma_bf16(acc[mt][nt], ah[mt], B2l);
                    mma_bf16(acc[mt][nt], al[mt], B2h);
                }
            }
        }
    }

#pragma unroll
    for (int mt = 0; mt < 4; mt++) {
        int r0 = rowBase + warp_m * 64 + mt * 16 + (lane >> 2);
#pragma unroll
        for (int nt = 0; nt < 4; nt++) {
            int col = colBase + warp_n * 32 + nt * 8 + (lane & 3) * 2;
#pragma unroll
            for (int half = 0; half < 2; half++) {
                int r = r0 + half * 8;
                if (r >= M) continue;
                size_t off = (size_t)r * DD + col;
                float2 v = make_float2(acc[mt][nt][half * 2], acc[mt][nt][half * 2 + 1]);
                if (resid) {
                    float2 rv = *reinterpret_cast<const float2*>(resid + off);
                    v.x += rv.x; v.y += rv.y;
                }
                *reinterpret_cast<float2*>(C + off) = v;
            }
        }
    }
}

// ---------------- conversions ----------------
__global__ __launch_bounds__(256) void conv_emb(const float* __restrict__ emb) {
    int idx = blockIdx.x * 256 + threadIdx.x;
    if (idx >= NN * DD / 4) return;
    float4 x = reinterpret_cast<const float4*>(emb)[idx];
    __nv_bfloat16 h0 = __float2bfloat16(x.x);
    __nv_bfloat16 h1 = __float2bfloat16(x.y);
    __nv_bfloat16 h2 = __float2bfloat16(x.z);
    __nv_bfloat16 h3 = __float2bfloat16(x.w);
    __nv_bfloat162 hi01, hi23, lo01, lo23;
    hi01.x = h0; hi01.y = h1; hi23.x = h2; hi23.y = h3;
    lo01.x = __float2bfloat16(x.x - __bfloat162float(h0));
    lo01.y = __float2bfloat16(x.y - __bfloat162float(h1));
    lo23.x = __float2bfloat16(x.z - __bfloat162float(h2));
    lo23.y = __float2bfloat16(x.w - __bfloat162float(h3));
    uint2 hiv = make_uint2(*reinterpret_cast<uint32_t*>(&hi01), *reinterpret_cast<uint32_t*>(&hi23));
    uint2 lov = make_uint2(*reinterpret_cast<uint32_t*>(&lo01), *reinterpret_cast<uint32_t*>(&lo23));
    reinterpret_cast<uint2*>(g_emb_hi)[idx] = hiv;
    reinterpret_cast<uint2*>(g_emb_lo)[idx] = lov;
}

__global__ __launch_bounds__(256) void conv_weights(
    const float* __restrict__ WQ, const float* __restrict__ WK,
    const float* __restrict__ WV, const float* __restrict__ WO)
{
    int idx = blockIdx.x * 256 + threadIdx.x;
    if (idx >= 4 * DD * DD) return;
    int mat = idx / (DD * DD);
    int rem = idx - mat * (DD * DD);
    int n = rem / DD;
    int k = rem - n * DD;
    const float* W = (mat == 0) ? WQ : (mat == 1 ? WK : (mat == 2 ? WV : WO));
    float x = W[(size_t)k * DD + n];
    __nv_bfloat16 hi = __float2bfloat16(x);
    __nv_bfloat16 lo = __float2bfloat16(x - __bfloat162float(hi));
    if (mat < 3) {
        size_t o = (size_t)mat * DD * DD + (size_t)n * DD + k;
        g_wt_hi[o] = hi; g_wt_lo[o] = lo;
    } else {
        size_t o = (size_t)n * DD + k;
        g_wo_hi[o] = hi; g_wo_lo[o] = lo;
    }
}

// ---------------- CSR build (side stream) ----------------
__global__ __launch_bounds__(256) void zero_deg() {
    int i = blockIdx.x * 256 + threadIdx.x;
    if (i < NN) g_deg[i] = 0;
}

__global__ __launch_bounds__(256) void hist_kernel(const int* __restrict__ dst) {
    int e = blockIdx.x * 256 + threadIdx.x;
    if (e < EE) atomicAdd(&g_deg[dst[e]], 1);
}

__device__ __forceinline__ int warp_incl_scan(int x, int lane) {
#pragma unroll
    for (int off = 1; off < 32; off <<= 1) {
        int v = __shfl_up_sync(0xffffffffu, x, off);
        if (lane >= off) x += v;
    }
    return x;
}

__global__ __launch_bounds__(1024) void scanA() {
    __shared__ int swarp[32];
    const int tid = threadIdx.x;
    const int w = tid >> 5, lane = tid & 31;
    int idx = blockIdx.x * 1024 + tid;
    int x = (idx < NN) ? g_deg[idx] : 0;
    int incl = warp_incl_scan(x, lane);
    if (lane == 31) swarp[w] = incl;
    __syncthreads();
    if (w == 0) {
        int t = swarp[lane];
        t = warp_incl_scan(t, lane);
        swarp[lane] = t;
    }
    __syncthreads();
    int woff = (w > 0) ? swarp[w - 1] : 0;
    incl += woff;
    if (idx < NN) g_rowptr[idx] = incl;
    if (tid == 1023) g_blocksum[blockIdx.x] = incl;
}

__global__ __launch_bounds__(64) void scanB() {
    __shared__ int sh[64];
    const int tid = threadIdx.x;
    int v = (tid < NSCAN) ? g_blocksum[tid] : 0;
    sh[tid] = v;
    for (int off = 1; off < 64; off <<= 1) {
        __syncthreads();
        int t = (tid >= off) ? sh[tid - off] : 0;
        __syncthreads();
        sh[tid] += t;
    }
    __syncthreads();
    if (tid < NSCAN) g_blocksum[tid] = sh[tid] - v;  // exclusive
    if (tid == 63) g_rowptr[NN] = sh[63];
}

__global__ __launch_bounds__(1024) void scanC() {
    int idx = blockIdx.x * 1024 + threadIdx.x;
    if (idx >= NN) return;
    int ex = g_blocksum[blockIdx.x] + g_rowptr[idx] - g_deg[idx];
    g_rowptr[idx] = ex;
    g_cursor[idx] = ex;
}

__global__ __launch_bounds__(256) void scatter_kernel(
    const int* __restrict__ src, const int* __restrict__ dst,
    const float* __restrict__ eattr)
{
    int e = blockIdx.x * 256 + threadIdx.x;
    if (e >= EE) return;
    int t = dst[e];
    int pos = atomicAdd(&g_cursor[t], 1);
    g_esrc[pos] = src[e];
    g_eea[pos] = eattr[e];
}

// ---------------- fused attention aggregate: warp per (node, head) ----------------
__global__ __launch_bounds__(256) void node_fused(const float* __restrict__ WE) {
    const int gw = blockIdx.x * 8 + (threadIdx.x >> 5);
    const int n = gw >> 1;
    if (n >= NN) return;
    const int h = gw & 1;
    const int hb = h * DHH;
    const int lane = threadIdx.x & 31;

    float qv[6], we[6];
    const float* qrow = g_q + (size_t)n * DD + hb;
    const float* werow = WE + hb;
#pragma unroll
    for (int j = 0; j < 6; j++) {
        int d = lane + 32 * j;
        qv[j] = qrow[d];
        we[j] = werow[d];
    }

    // qe = q_h . WE_h
    float qe = 0.f;
#pragma unroll
    for (int j = 0; j < 6; j++) qe += qv[j] * we[j];
#pragma unroll
    for (int o = 16; o > 0; o >>= 1) qe += __shfl_xor_sync(0xffffffffu, qe, o);

    const int beg = g_rowptr[n];
    const int end = g_rowptr[n + 1];

    float m0 = -3.0e38f, den = 0.f, sexa = 0.f;
    float acc[6];
#pragma unroll
    for (int j = 0; j < 6; j++) acc[j] = 0.f;

    const float SCL = 0.07216878364870323f;  // 1/sqrt(192)

    for (int i = beg; i < end; i++) {
        const int s = g_esrc[i];
        const float ea = g_eea[i];
        const float* krow = g_k + (size_t)s * DD + hb;
        const float* vrow = g_v + (size_t)s * DD + hb;

        float kv[6], vv[6];
#pragma unroll
        for (int j = 0; j < 6; j++) {
            int d = lane + 32 * j;
            kv[j] = krow[d];
            vv[j] = vrow[d];
        }
        float ds = 0.f;
#pragma unroll
        for (int j = 0; j < 6; j++) ds += qv[j] * kv[j];
#pragma unroll
        for (int o = 16; o > 0; o >>= 1) ds += __shfl_xor_sync(0xffffffffu, ds, o);
        float s0 = (ds + ea * qe) * SCL;

        float nm = fmaxf(m0, s0);
        float sc = __expf(m0 - nm);
        float ex = __expf(s0 - nm);
        den = den * sc + ex;
        sexa = sexa * sc + ex * ea;
#pragma unroll
        for (int j = 0; j < 6; j++) acc[j] = acc[j] * sc + ex * vv[j];
        m0 = nm;
    }

    const float inv = 1.0f / (den + 1e-16f);
    size_t base = (size_t)n * DD + hb;
#pragma unroll
    for (int j = 0; j < 6; j++) {
        int d = lane + 32 * j;
        float o0 = (acc[j] + sexa * we[j]) * inv;
        __nv_bfloat16 hi = __float2bfloat16(o0);
        g_agg_hi[base + d] = hi;
        g_agg_lo[base + d] = __float2bfloat16(o0 - __bfloat162float(hi));
    }
}

// ---------------- layernorm: warp per row, float4 ----------------
__global__ __launch_bounds__(256) void ln_kernel(
    const float* __restrict__ gw, const float* __restrict__ bw,
    float* __restrict__ out)
{
    const int n = blockIdx.x * 8 + (threadIdx.x >> 5);
    if (n >= NN) return;
    const int lane = threadIdx.x & 31;
    const float4* x = reinterpret_cast<const float4*>(g_tmp + (size_t)n * DD);
    float4 v[3];
    float su = 0.f, sq = 0.f;
#pragma unroll
    for (int j = 0; j < 3; j++) {
        v[j] = x[lane + 32 * j];
        su += v[j].x + v[j].y + v[j].z + v[j].w;
        sq += v[j].x * v[j].x + v[j].y * v[j].y + v[j].z * v[j].z + v[j].w * v[j].w;
    }
#pragma unroll
    for (int o = 16; o > 0; o >>= 1) {
        su += __shfl_xor_sync(0xffffffffu, su, o);
        sq += __shfl_xor_sync(0xffffffffu, sq, o);
    }
    float mu = su * (1.0f / DD);
    float var = sq * (1.0f / DD) - mu * mu;
    float inv = rsqrtf(var + 1e-5f);
    const float4* g4 = reinterpret_cast<const float4*>(gw);
    const float4* b4 = reinterpret_cast<const float4*>(bw);
    float4* o4 = reinterpret_cast<float4*>(out + (size_t)n * DD);
#pragma unroll
    for (int j = 0; j < 3; j++) {
        float4 g = g4[lane + 32 * j];
        float4 b = b4[lane + 32 * j];
        float4 r;
        r.x = (v[j].x - mu) * inv * g.x + b.x;
        r.y = (v[j].y - mu) * inv * g.y + b.y;
        r.z = (v[j].z - mu) * inv * g.z + b.z;
        r.w = (v[j].w - mu) * inv * g.w + b.w;
        o4[lane + 32 * j] = r;
    }
}

// ---------------- launch ----------------
extern "C" void kernel_launch(void* const* d_in, const int* in_sizes, int n_in,
                              void* d_out, int out_size)
{
    const float* emb   = (const float*)d_in[0];
    const int*   eidx  = (const int*)  d_in[1];
    const float* eattr = (const float*)d_in[2];
    const float* WQ    = (const float*)d_in[3];
    const float* WK    = (const float*)d_in[4];
    const float* WV    = (const float*)d_in[5];
    const float* WE    = (const float*)d_in[6];
    const float* WO    = (const float*)d_in[7];
    const float* ln_g  = (const float*)d_in[8];
    const float* ln_b  = (const float*)d_in[9];
    float* out = (float*)d_out;

    const int* src = eidx;
    const int* dst = eidx + EE;

    static bool inited = false;
    static cudaStream_t s_side;
    static cudaEvent_t ev_fork, ev_join, ev_w;
    if (!inited) {
        cudaFuncSetAttribute(gemm_tc, cudaFuncAttributeMaxDynamicSharedMemorySize, SM_TOTAL);
        cudaStreamCreateWithFlags(&s_side, cudaStreamNonBlocking);
        cudaEventCreateWithFlags(&ev_fork, cudaEventDisableTiming);
        cudaEventCreateWithFlags(&ev_join, cudaEventDisableTiming);
        cudaEventCreateWithFlags(&ev_w, cudaEventDisableTiming);
        inited = true;
    }

    float *dq, *dk, *dv, *dtmp;
    __nv_bfloat16 *dembh, *dembl, *daggh, *daggl, *dwth, *dwtl, *dwoh, *dwol;
    cudaGetSymbolAddress((void**)&dq,    g_q);
    cudaGetSymbolAddress((void**)&dk,    g_k);
    cudaGetSymbolAddress((void**)&dv,    g_v);
    cudaGetSymbolAddress((void**)&dtmp,  g_tmp);
    cudaGetSymbolAddress((void**)&dembh, g_emb_hi);
    cudaGetSymbolAddress((void**)&dembl, g_emb_lo);
    cudaGetSymbolAddress((void**)&daggh, g_agg_hi);
    cudaGetSymbolAddress((void**)&daggl, g_agg_lo);
    cudaGetSymbolAddress((void**)&dwth,  g_wt_hi);
    cudaGetSymbolAddress((void**)&dwtl,  g_wt_lo);
    cudaGetSymbolAddress((void**)&dwoh,  g_wo_hi);
    cudaGetSymbolAddress((void**)&dwol,  g_wo_lo);

    // ---- fork: weights conversion + CSR build on side stream ----
    cudaEventRecord(ev_fork, 0);
    cudaStreamWaitEvent(s_side, ev_fork, 0);
    conv_weights<<<(4 * DD * DD + 255) / 256, 256, 0, s_side>>>(WQ, WK, WV, WO);
    cudaEventRecord(ev_w, s_side);
    zero_deg<<<(NN + 255) / 256, 256, 0, s_side>>>();
    hist_kernel<<<(EE + 255) / 256, 256, 0, s_side>>>(dst);
    scanA<<<NSCAN, 1024, 0, s_side>>>();
    scanB<<<1, 64, 0, s_side>>>();
    scanC<<<NSCAN, 1024, 0, s_side>>>();
    scatter_kernel<<<(EE + 255) / 256, 256, 0, s_side>>>(src, dst, eattr);
    cudaEventRecord(ev_join, s_side);

    // ---- main stream: emb conversion + QKV projections ----
    conv_emb<<<(NN * DD / 4 + 255) / 256, 256>>>(emb);
    cudaStreamWaitEvent(0, ev_w, 0);

    const int MT = (NN + 127) / 128;
    gemm_tc<<<dim3(9, MT), 256, SM_TOTAL>>>(dembh, dembl, dwth, dwtl,
                                            dq, dk, dv, NN, nullptr);

    // ---- join, then fused attention ----
    cudaStreamWaitEvent(0, ev_join, 0);
    node_fused<<<(2 * NN + 7) / 8, 256>>>(WE);

    // output projection + residual
    gemm_tc<<<dim3(3, MT), 256, SM_TOTAL>>>(daggh, daggl, dwoh, dwol,
                                            dtmp, dtmp, dtmp, NN, emb);

    // layernorm -> out
    ln_kernel<<<(NN + 7) / 8, 256>>>(ln_g, ln_b, out);
}

// round 12
// speedup vs baseline: 1.4828x; 1.2764x over previous
#include <cuda_runtime.h>
#include <cuda_fp16.h>
#include <math.h>
#include <stdint.h>

// Problem constants (fixed by the reference)
#define NN 50000
#define EE 200000
#define DD 384
#define HH 2
#define DHH 192

#define SCAN_BLK 1024
#define NSCAN ((NN + SCAN_BLK - 1) / SCAN_BLK)   // 49

// ---------------- device scratch (allocation-free requirement) ----------------
__device__ float g_q[(size_t)NN * DD];
__device__ float g_k[(size_t)NN * DD];
__device__ float g_v[(size_t)NN * DD];
__device__ float g_tmp[(size_t)NN * DD];

__device__ int   g_deg[NN];
__device__ int   g_rowptr[NN + 1];
__device__ int   g_cursor[NN];
__device__ int   g_blocksum[NSCAN];
__device__ int   g_esrc[EE];
__device__ float g_eea[EE];

__device__ __half g_emb[(size_t)NN * DD];            // fp16(A)
__device__ __half g_agg[(size_t)NN * DD];            // fp16(agg)
__device__ __half g_wt_hi[(size_t)3 * DD * DD];      // [WQ|WK|WV]^T  [1152(N), 384(K)]
__device__ __half g_wt_lo[(size_t)3 * DD * DD];
__device__ __half g_wo_hi[(size_t)DD * DD];          // WO^T [384, 384]
__device__ __half g_wo_lo[(size_t)DD * DD];

// ---------------- PTX helpers (baseline features only; PTX target is compute_103) ----------------
__device__ __forceinline__ uint32_t smem_to_u32(const void* p) {
    uint32_t a;
    asm("{ .reg .u64 t; cvta.to.shared.u64 t, %1; cvt.u32.u64 %0, t; }" : "=r"(a) : "l"(p));
    return a;
}
__device__ __forceinline__ void ldsm_x4(uint32_t* r, uint32_t addr) {
    asm volatile("ldmatrix.sync.aligned.m8n8.x4.shared.b16 {%0,%1,%2,%3}, [%4];"
        : "=r"(r[0]), "=r"(r[1]), "=r"(r[2]), "=r"(r[3]) : "r"(addr));
}
__device__ __forceinline__ void mma_f16(float* c, const uint32_t* a, const uint32_t* b) {
    asm volatile(
        "mma.sync.aligned.m16n8k16.row.col.f32.f16.f16.f32 "
        "{%0,%1,%2,%3}, {%4,%5,%6,%7}, {%8,%9}, {%0,%1,%2,%3};"
        : "+f"(c[0]), "+f"(c[1]), "+f"(c[2]), "+f"(c[3])
        : "r"(a[0]), "r"(a[1]), "r"(a[2]), "r"(a[3]), "r"(b[0]), "r"(b[1]));
}
__device__ __forceinline__ void cp16(uint32_t dst, const void* src, bool valid) {
    int sz = valid ? 16 : 0;
    asm volatile("cp.async.cg.shared.global [%0], [%1], 16, %2;"
        :: "r"(dst), "l"(src), "r"(sz) : "memory");
}

// smem geometry: 3 operand arrays (A, Bhi, Blo), 128 rows x 80B pitch, double-buffered
// 60 KB/CTA; occupancy reg-limited at 2 CTAs/SM.
#define PITCH 80
#define ARR   10240          // 128 * 80
#define STG   30720          // 3 * ARR
#define SM_TOTAL (2 * STG)   // 61440

// ---------------- fp16x2 HMMA GEMM ----------------
// C[m, colBase+n] = sum_k A[m,k] * (Bthi+Btlo)[bx*128+n, k]  (+resid)
__global__ __launch_bounds__(256)
void gemm_tc(const __half* __restrict__ A,
             const __half* __restrict__ Bhi, const __half* __restrict__ Blo,
             float* __restrict__ C0, float* __restrict__ C1, float* __restrict__ C2,
             int M, const float* __restrict__ resid)
{
    extern __shared__ char smem[];
    const uint32_t sb = smem_to_u32(smem);
    const int tid = threadIdx.x;
    const int wid = tid >> 5;
    const int lane = tid & 31;
    const int warp_m = wid & 1;
    const int warp_n = wid >> 1;
    const int rowBase = blockIdx.y * 128;
    const int mat = blockIdx.x / 3;
    const int colBase = (blockIdx.x % 3) * 128;
    const int btRowBase = blockIdx.x * 128;
    float* C = (mat == 0) ? C0 : (mat == 1 ? C1 : C2);

    float acc[4][4][4];
#pragma unroll
    for (int i = 0; i < 4; i++)
#pragma unroll
        for (int j = 0; j < 4; j++)
#pragma unroll
            for (int l = 0; l < 4; l++) acc[i][j][l] = 0.0f;

    const __half* srcs[3] = { A, Bhi, Blo };

    // stage = 3 arrays x 128 rows x 4 chunks of 16B => 1536 cp16, 6 per thread
    auto load_stage = [&](int buf, int s) {
        const int k0 = s * 32;
#pragma unroll
        for (int i = 0; i < 6; i++) {
            int id = i * 256 + tid;          // 0..1535
            int arr = id >> 9;               // 0..2
            int cid = id & 511;
            int row = cid >> 2;              // 0..127
            int c = cid & 3;                 // 16B chunk
            uint32_t dst = sb + buf * STG + arr * ARR + row * PITCH + c * 16;
            const __half* src;
            bool valid = true;
            if (arr == 0) {
                int gRow = rowBase + row;
                valid = (gRow < M);
                int gr = valid ? gRow : 0;
                src = srcs[0] + (size_t)gr * DD + k0 + c * 8;
            } else {
                src = srcs[arr] + (size_t)(btRowBase + row) * DD + k0 + c * 8;
            }
            cp16(dst, src, valid);
        }
        asm volatile("cp.async.commit_group;" ::: "memory");
    };

    load_stage(0, 0);

    for (int s = 0; s < 12; s++) {
        asm volatile("cp.async.wait_group 0;" ::: "memory");
        __syncthreads();                         // single barrier per stage
        if (s + 1 < 12) load_stage((s + 1) & 1, s + 1);   // overlaps compute(s)

        const uint32_t st = sb + (s & 1) * STG;
#pragma unroll
        for (int kk = 0; kk < 2; kk++) {
            uint32_t ah[4][4], bh[2][4], bl[2][4];
            const int arow = warp_m * 64;
#pragma unroll
            for (int mt = 0; mt < 4; mt++) {
                uint32_t addr = st + (uint32_t)((arow + mt * 16 + (lane & 15)) * PITCH
                              + kk * 32 + ((lane >> 4) & 1) * 16);
                ldsm_x4(ah[mt], addr);
            }
#pragma unroll
            for (int p = 0; p < 2; p++) {
                int grp = lane >> 3;
                int row = warp_n * 32 + (p * 2 + (grp >> 1)) * 8 + (lane & 7);
                uint32_t addr = st + ARR + (uint32_t)(row * PITCH
                              + kk * 32 + (grp & 1) * 16);
                ldsm_x4(bh[p], addr);
                ldsm_x4(bl[p], addr + ARR);
            }
#pragma unroll
            for (int mt = 0; mt < 4; mt++) {
#pragma unroll
                for (int nt = 0; nt < 4; nt++) {
                    const uint32_t* B2h = &bh[nt >> 1][(nt & 1) * 2];
                    const uint32_t* B2l = &bl[nt >> 1][(nt & 1) * 2];
                    mma_f16(acc[mt][nt], ah[mt], B2h);
                    mma_f16(acc[mt][nt], ah[mt], B2l);
                }
            }
        }
    }

#pragma unroll
    for (int mt = 0; mt < 4; mt++) {
        int r0 = rowBase + warp_m * 64 + mt * 16 + (lane >> 2);
#pragma unroll
        for (int nt = 0; nt < 4; nt++) {
            int col = colBase + warp_n * 32 + nt * 8 + (lane & 3) * 2;
#pragma unroll
            for (int half = 0; half < 2; half++) {
                int r = r0 + half * 8;
                if (r >= M) continue;
                size_t off = (size_t)r * DD + col;
                float2 v = make_float2(acc[mt][nt][half * 2], acc[mt][nt][half * 2 + 1]);
                if (resid) {
                    float2 rv = *reinterpret_cast<const float2*>(resid + off);
                    v.x += rv.x; v.y += rv.y;
                }
                *reinterpret_cast<float2*>(C + off) = v;
            }
        }
    }
}

// ---------------- conversions ----------------
// emb -> fp16 (hi only), 4 elements per thread
__global__ __launch_bounds__(256) void conv_emb(const float* __restrict__ emb) {
    int idx = blockIdx.x * 256 + threadIdx.x;
    if (idx >= NN * DD / 4) return;
    float4 x = reinterpret_cast<const float4*>(emb)[idx];
    __half2 a, b;
    a.x = __float2half_rn(x.x); a.y = __float2half_rn(x.y);
    b.x = __float2half_rn(x.z); b.y = __float2half_rn(x.w);
    uint2 v = make_uint2(*reinterpret_cast<uint32_t*>(&a), *reinterpret_cast<uint32_t*>(&b));
    reinterpret_cast<uint2*>(g_emb)[idx] = v;
}

// weights transpose + fp16 hi/lo split
__global__ __launch_bounds__(256) void conv_weights(
    const float* __restrict__ WQ, const float* __restrict__ WK,
    const float* __restrict__ WV, const float* __restrict__ WO)
{
    int idx = blockIdx.x * 256 + threadIdx.x;
    if (idx >= 4 * DD * DD) return;
    int mat = idx / (DD * DD);
    int rem = idx - mat * (DD * DD);
    int n = rem / DD;
    int k = rem - n * DD;
    const float* W = (mat == 0) ? WQ : (mat == 1 ? WK : (mat == 2 ? WV : WO));
    float x = W[(size_t)k * DD + n];
    __half hi = __float2half_rn(x);
    __half lo = __float2half_rn(x - __half2float(hi));
    if (mat < 3) {
        size_t o = (size_t)mat * DD * DD + (size_t)n * DD + k;
        g_wt_hi[o] = hi; g_wt_lo[o] = lo;
    } else {
        size_t o = (size_t)n * DD + k;
        g_wo_hi[o] = hi; g_wo_lo[o] = lo;
    }
}

// ---------------- CSR build (side stream) ----------------
__global__ __launch_bounds__(256) void zero_deg() {
    int i = blockIdx.x * 256 + threadIdx.x;
    if (i < NN) g_deg[i] = 0;
}

__global__ __launch_bounds__(256) void hist_kernel(const int* __restrict__ dst) {
    int e = blockIdx.x * 256 + threadIdx.x;
    if (e < EE) atomicAdd(&g_deg[dst[e]], 1);
}

__device__ __forceinline__ int warp_incl_scan(int x, int lane) {
#pragma unroll
    for (int off = 1; off < 32; off <<= 1) {
        int v = __shfl_up_sync(0xffffffffu, x, off);
        if (lane >= off) x += v;
    }
    return x;
}

__global__ __launch_bounds__(1024) void scanA() {
    __shared__ int swarp[32];
    const int tid = threadIdx.x;
    const int w = tid >> 5, lane = tid & 31;
    int idx = blockIdx.x * 1024 + tid;
    int x = (idx < NN) ? g_deg[idx] : 0;
    int incl = warp_incl_scan(x, lane);
    if (lane == 31) swarp[w] = incl;
    __syncthreads();
    if (w == 0) {
        int t = swarp[lane];
        t = warp_incl_scan(t, lane);
        swarp[lane] = t;
    }
    __syncthreads();
    int woff = (w > 0) ? swarp[w - 1] : 0;
    incl += woff;
    if (idx < NN) g_rowptr[idx] = incl;
    if (tid == 1023) g_blocksum[blockIdx.x] = incl;
}

__global__ __launch_bounds__(64) void scanB() {
    __shared__ int sh[64];
    const int tid = threadIdx.x;
    int v = (tid < NSCAN) ? g_blocksum[tid] : 0;
    sh[tid] = v;
    for (int off = 1; off < 64; off <<= 1) {
        __syncthreads();
        int t = (tid >= off) ? sh[tid - off] : 0;
        __syncthreads();
        sh[tid] += t;
    }
    __syncthreads();
    if (tid < NSCAN) g_blocksum[tid] = sh[tid] - v;  // exclusive
    if (tid == 63) g_rowptr[NN] = sh[63];
}

__global__ __launch_bounds__(1024) void scanC() {
    int idx = blockIdx.x * 1024 + threadIdx.x;
    if (idx >= NN) return;
    int ex = g_blocksum[blockIdx.x] + g_rowptr[idx] - g_deg[idx];
    g_rowptr[idx] = ex;
    g_cursor[idx] = ex;
}

__global__ __launch_bounds__(256) void scatter_kernel(
    const int* __restrict__ src, const int* __restrict__ dst,
    const float* __restrict__ eattr)
{
    int e = blockIdx.x * 256 + threadIdx.x;
    if (e >= EE) return;
    int t = dst[e];
    int pos = atomicAdd(&g_cursor[t], 1);
    g_esrc[pos] = src[e];
    g_eea[pos] = eattr[e];
}

// ---------------- fused attention aggregate: warp per (node, head) ----------------
__global__ __launch_bounds__(256) void node_fused(const float* __restrict__ WE) {
    const int gw = blockIdx.x * 8 + (threadIdx.x >> 5);
    const int n = gw >> 1;
    if (n >= NN) return;
    const int h = gw & 1;
    const int hb = h * DHH;
    const int lane = threadIdx.x & 31;

    float qv[6], we[6];
    const float* qrow = g_q + (size_t)n * DD + hb;
    const float* werow = WE + hb;
#pragma unroll
    for (int j = 0; j < 6; j++) {
        int d = lane + 32 * j;
        qv[j] = qrow[d];
        we[j] = werow[d];
    }

    // qe = q_h . WE_h
    float qe = 0.f;
#pragma unroll
    for (int j = 0; j < 6; j++) qe += qv[j] * we[j];
#pragma unroll
    for (int o = 16; o > 0; o >>= 1) qe += __shfl_xor_sync(0xffffffffu, qe, o);

    const int beg = g_rowptr[n];
    const int end = g_rowptr[n + 1];

    float m0 = -3.0e38f, den = 0.f, sexa = 0.f;
    float acc[6];
#pragma unroll
    for (int j = 0; j < 6; j++) acc[j] = 0.f;

    const float SCL = 0.07216878364870323f;  // 1/sqrt(192)

    for (int i = beg; i < end; i++) {
        const int s = g_esrc[i];
        const float ea = g_eea[i];
        const float* krow = g_k + (size_t)s * DD + hb;
        const float* vrow = g_v + (size_t)s * DD + hb;

        float kv[6], vv[6];
#pragma unroll
        for (int j = 0; j < 6; j++) {
            int d = lane + 32 * j;
            kv[j] = krow[d];
            vv[j] = vrow[d];
        }
        float ds = 0.f;
#pragma unroll
        for (int j = 0; j < 6; j++) ds += qv[j] * kv[j];
#pragma unroll
        for (int o = 16; o > 0; o >>= 1) ds += __shfl_xor_sync(0xffffffffu, ds, o);
        float s0 = (ds + ea * qe) * SCL;

        float nm = fmaxf(m0, s0);
        float sc = __expf(m0 - nm);
        float ex = __expf(s0 - nm);
        den = den * sc + ex;
        sexa = sexa * sc + ex * ea;
#pragma unroll
        for (int j = 0; j < 6; j++) acc[j] = acc[j] * sc + ex * vv[j];
        m0 = nm;
    }

    const float inv = 1.0f / (den + 1e-16f);
    size_t base = (size_t)n * DD + hb;
#pragma unroll
    for (int j = 0; j < 6; j++) {
        int d = lane + 32 * j;
        float o0 = (acc[j] + sexa * we[j]) * inv;
        g_agg[base + d] = __float2half_rn(o0);
    }
}

// ---------------- layernorm: warp per row, float4 ----------------
__global__ __launch_bounds__(256) void ln_kernel(
    const float* __restrict__ gw, const float* __restrict__ bw,
    float* __restrict__ out)
{
    const int n = blockIdx.x * 8 + (threadIdx.x >> 5);
    if (n >= NN) return;
    const int lane = threadIdx.x & 31;
    const float4* x = reinterpret_cast<const float4*>(g_tmp + (size_t)n * DD);
    float4 v[3];
    float su = 0.f, sq = 0.f;
#pragma unroll
    for (int j = 0; j < 3; j++) {
        v[j] = x[lane + 32 * j];
        su += v[j].x + v[j].y + v[j].z + v[j].w;
        sq += v[j].x * v[j].x + v[j].y * v[j].y + v[j].z * v[j].z + v[j].w * v[j].w;
    }
#pragma unroll
    for (int o = 16; o > 0; o >>= 1) {
        su += __shfl_xor_sync(0xffffffffu, su, o);
        sq += __shfl_xor_sync(0xffffffffu, sq, o);
    }
    float mu = su * (1.0f / DD);
    float var = sq * (1.0f / DD) - mu * mu;
    float inv = rsqrtf(var + 1e-5f);
    const float4* g4 = reinterpret_cast<const float4*>(gw);
    const float4* b4 = reinterpret_cast<const float4*>(bw);
    float4* o4 = reinterpret_cast<float4*>(out + (size_t)n * DD);
#pragma unroll
    for (int j = 0; j < 3; j++) {
        float4 g = g4[lane + 32 * j];
        float4 b = b4[lane + 32 * j];
        float4 r;
        r.x = (v[j].x - mu) * inv * g.x + b.x;
        r.y = (v[j].y - mu) * inv * g.y + b.y;
        r.z = (v[j].z - mu) * inv * g.z + b.z;
        r.w = (v[j].w - mu) * inv * g.w + b.w;
        o4[lane + 32 * j] = r;
    }
}

// ---------------- launch ----------------
extern "C" void kernel_launch(void* const* d_in, const int* in_sizes, int n_in,
                              void* d_out, int out_size)
{
    const float* emb   = (const float*)d_in[0];
    const int*   eidx  = (const int*)  d_in[1];
    const float* eattr = (const float*)d_in[2];
    const float* WQ    = (const float*)d_in[3];
    const float* WK    = (const float*)d_in[4];
    const float* WV    = (const float*)d_in[5];
    const float* WE    = (const float*)d_in[6];
    const float* WO    = (const float*)d_in[7];
    const float* ln_g  = (const float*)d_in[8];
    const float* ln_b  = (const float*)d_in[9];
    float* out = (float*)d_out;

    const int* src = eidx;
    const int* dst = eidx + EE;

    static bool inited = false;
    static cudaStream_t s_side;
    static cudaEvent_t ev_fork, ev_join, ev_w;
    if (!inited) {
        cudaFuncSetAttribute(gemm_tc, cudaFuncAttributeMaxDynamicSharedMemorySize, SM_TOTAL);
        cudaStreamCreateWithFlags(&s_side, cudaStreamNonBlocking);
        cudaEventCreateWithFlags(&ev_fork, cudaEventDisableTiming);
        cudaEventCreateWithFlags(&ev_join, cudaEventDisableTiming);
        cudaEventCreateWithFlags(&ev_w, cudaEventDisableTiming);
        inited = true;
    }

    float *dq, *dk, *dv, *dtmp;
    __half *demb, *dagg, *dwth, *dwtl, *dwoh, *dwol;
    cudaGetSymbolAddress((void**)&dq,   g_q);
    cudaGetSymbolAddress((void**)&dk,   g_k);
    cudaGetSymbolAddress((void**)&dv,   g_v);
    cudaGetSymbolAddress((void**)&dtmp, g_tmp);
    cudaGetSymbolAddress((void**)&demb, g_emb);
    cudaGetSymbolAddress((void**)&dagg, g_agg);
    cudaGetSymbolAddress((void**)&dwth, g_wt_hi);
    cudaGetSymbolAddress((void**)&dwtl, g_wt_lo);
    cudaGetSymbolAddress((void**)&dwoh, g_wo_hi);
    cudaGetSymbolAddress((void**)&dwol, g_wo_lo);

    // ---- fork: weights conversion + CSR build on side stream ----
    cudaEventRecord(ev_fork, 0);
    cudaStreamWaitEvent(s_side, ev_fork, 0);
    conv_weights<<<(4 * DD * DD + 255) / 256, 256, 0, s_side>>>(WQ, WK, WV, WO);
    cudaEventRecord(ev_w, s_side);
    zero_deg<<<(NN + 255) / 256, 256, 0, s_side>>>();
    hist_kernel<<<(EE + 255) / 256, 256, 0, s_side>>>(dst);
    scanA<<<NSCAN, 1024, 0, s_side>>>();
    scanB<<<1, 64, 0, s_side>>>();
    scanC<<<NSCAN, 1024, 0, s_side>>>();
    scatter_kernel<<<(EE + 255) / 256, 256, 0, s_side>>>(src, dst, eattr);
    cudaEventRecord(ev_join, s_side);

    // ---- main stream: emb conversion + QKV projections ----
    conv_emb<<<(NN * DD / 4 + 255) / 256, 256>>>(emb);
    cudaStreamWaitEvent(0, ev_w, 0);

    const int MT = (NN + 127) / 128;
    gemm_tc<<<dim3(9, MT), 256, SM_TOTAL>>>(demb, dwth, dwtl,
                                            dq, dk, dv, NN, nullptr);

    // ---- join, then fused attention ----
    cudaStreamWaitEvent(0, ev_join, 0);
    node_fused<<<(2 * NN + 7) / 8, 256>>>(WE);

    // output projection + residual
    gemm_tc<<<dim3(3, MT), 256, SM_TOTAL>>>(dagg, dwoh, dwol,
                                            dtmp, dtmp, dtmp, NN, emb);

    // layernorm -> out
    ln_kernel<<<(NN + 7) / 8, 256>>>(ln_g, ln_b, out);
}

// round 13
// speedup vs baseline: 1.8926x; 1.2763x over previous
#include <cuda_runtime.h>
#include <cuda_fp16.h>
#include <math.h>
#include <stdint.h>

// Problem constants (fixed by the reference)
#define NN 50000
#define EE 200000
#define DD 384
#define HH 2
#define DHH 192

#define SCAN_BLK 1024
#define NSCAN ((NN + SCAN_BLK - 1) / SCAN_BLK)   // 49

// ---------------- device scratch (allocation-free requirement) ----------------
__device__ float g_q[(size_t)NN * DD];
__device__ float g_k[(size_t)NN * DD];
__device__ float g_v[(size_t)NN * DD];
__device__ float g_tmp[(size_t)NN * DD];

__device__ int   g_deg[NN];
__device__ int   g_rowptr[NN + 1];
__device__ int   g_cursor[NN];
__device__ int   g_blocksum[NSCAN];
__device__ int   g_esrc[EE];
__device__ float g_eea[EE];

__device__ __half g_emb[(size_t)NN * DD];        // fp16(A)
__device__ __half g_agg[(size_t)NN * DD];        // fp16(agg)
__device__ __half g_wt[(size_t)3 * DD * DD];     // [WQ|WK|WV]^T  [1152(N), 384(K)]
__device__ __half g_wo[(size_t)DD * DD];         // WO^T [384, 384]

// ---------------- PTX helpers (baseline features only; PTX target is compute_103) ----------------
__device__ __forceinline__ uint32_t smem_to_u32(const void* p) {
    uint32_t a;
    asm("{ .reg .u64 t; cvta.to.shared.u64 t, %1; cvt.u32.u64 %0, t; }" : "=r"(a) : "l"(p));
    return a;
}
__device__ __forceinline__ void ldsm_x4(uint32_t* r, uint32_t addr) {
    asm volatile("ldmatrix.sync.aligned.m8n8.x4.shared.b16 {%0,%1,%2,%3}, [%4];"
        : "=r"(r[0]), "=r"(r[1]), "=r"(r[2]), "=r"(r[3]) : "r"(addr));
}
__device__ __forceinline__ void mma_f16(float* c, const uint32_t* a, const uint32_t* b) {
    asm volatile(
        "mma.sync.aligned.m16n8k16.row.col.f32.f16.f16.f32 "
        "{%0,%1,%2,%3}, {%4,%5,%6,%7}, {%8,%9}, {%0,%1,%2,%3};"
        : "+f"(c[0]), "+f"(c[1]), "+f"(c[2]), "+f"(c[3])
        : "r"(a[0]), "r"(a[1]), "r"(a[2]), "r"(a[3]), "r"(b[0]), "r"(b[1]));
}
__device__ __forceinline__ void cp16(uint32_t dst, const void* src, bool valid) {
    int sz = valid ? 16 : 0;
    asm volatile("cp.async.cg.shared.global [%0], [%1], 16, %2;"
        :: "r"(dst), "l"(src), "r"(sz) : "memory");
}

// smem geometry: 2 operand arrays (A, B), 128 rows x 80B pitch, double-buffered
// 40 KB/CTA; 2 CTAs/SM (reg-limited).
#define PITCH 80
#define ARR   10240          // 128 * 80
#define STG   20480          // 2 * ARR
#define SM_TOTAL (2 * STG)   // 40960

// ---------------- fp16 HMMA GEMM ----------------
// C[m, colBase+n] = sum_k A[m,k] * Bt[bx*128+n, k]  (+resid)
__global__ __launch_bounds__(256)
void gemm_tc(const __half* __restrict__ A, const __half* __restrict__ Bt,
             float* __restrict__ C0, float* __restrict__ C1, float* __restrict__ C2,
             int M, const float* __restrict__ resid)
{
    extern __shared__ char smem[];
    const uint32_t sb = smem_to_u32(smem);
    const int tid = threadIdx.x;
    const int wid = tid >> 5;
    const int lane = tid & 31;
    const int warp_m = wid & 1;
    const int warp_n = wid >> 1;
    const int rowBase = blockIdx.y * 128;
    const int mat = blockIdx.x / 3;
    const int colBase = (blockIdx.x % 3) * 128;
    const int btRowBase = blockIdx.x * 128;
    float* C = (mat == 0) ? C0 : (mat == 1 ? C1 : C2);

    float acc[4][4][4];
#pragma unroll
    for (int i = 0; i < 4; i++)
#pragma unroll
        for (int j = 0; j < 4; j++)
#pragma unroll
            for (int l = 0; l < 4; l++) acc[i][j][l] = 0.0f;

    // stage = 2 arrays x 128 rows x 4 chunks of 16B => 1024 cp16, 4 per thread
    auto load_stage = [&](int buf, int s) {
        const int k0 = s * 32;
#pragma unroll
        for (int i = 0; i < 4; i++) {
            int id = i * 256 + tid;          // 0..1023
            int arr = id >> 9;               // 0..1
            int cid = id & 511;
            int row = cid >> 2;              // 0..127
            int c = cid & 3;                 // 16B chunk
            uint32_t dst = sb + buf * STG + arr * ARR + row * PITCH + c * 16;
            const __half* src;
            bool valid = true;
            if (arr == 0) {
                int gRow = rowBase + row;
                valid = (gRow < M);
                int gr = valid ? gRow : 0;
                src = A + (size_t)gr * DD + k0 + c * 8;
            } else {
                src = Bt + (size_t)(btRowBase + row) * DD + k0 + c * 8;
            }
            cp16(dst, src, valid);
        }
        asm volatile("cp.async.commit_group;" ::: "memory");
    };

    load_stage(0, 0);

    for (int s = 0; s < 12; s++) {
        asm volatile("cp.async.wait_group 0;" ::: "memory");
        __syncthreads();                         // single barrier per stage
        if (s + 1 < 12) load_stage((s + 1) & 1, s + 1);   // overlaps compute(s)

        const uint32_t st = sb + (s & 1) * STG;
#pragma unroll
        for (int kk = 0; kk < 2; kk++) {
            uint32_t ah[4][4], bh[2][4];
            const int arow = warp_m * 64;
#pragma unroll
            for (int mt = 0; mt < 4; mt++) {
                uint32_t addr = st + (uint32_t)((arow + mt * 16 + (lane & 15)) * PITCH
                              + kk * 32 + ((lane >> 4) & 1) * 16);
                ldsm_x4(ah[mt], addr);
            }
#pragma unroll
            for (int p = 0; p < 2; p++) {
                int grp = lane >> 3;
                int row = warp_n * 32 + (p * 2 + (grp >> 1)) * 8 + (lane & 7);
                uint32_t addr = st + ARR + (uint32_t)(row * PITCH
                              + kk * 32 + (grp & 1) * 16);
                ldsm_x4(bh[p], addr);
            }
#pragma unroll
            for (int mt = 0; mt < 4; mt++) {
#pragma unroll
                for (int nt = 0; nt < 4; nt++) {
                    const uint32_t* B2 = &bh[nt >> 1][(nt & 1) * 2];
                    mma_f16(acc[mt][nt], ah[mt], B2);
                }
            }
        }
    }

#pragma unroll
    for (int mt = 0; mt < 4; mt++) {
        int r0 = rowBase + warp_m * 64 + mt * 16 + (lane >> 2);
#pragma unroll
        for (int nt = 0; nt < 4; nt++) {
            int col = colBase + warp_n * 32 + nt * 8 + (lane & 3) * 2;
#pragma unroll
            for (int half = 0; half < 2; half++) {
                int r = r0 + half * 8;
                if (r >= M) continue;
                size_t off = (size_t)r * DD + col;
                float2 v = make_float2(acc[mt][nt][half * 2], acc[mt][nt][half * 2 + 1]);
                if (resid) {
                    float2 rv = *reinterpret_cast<const float2*>(resid + off);
                    v.x += rv.x; v.y += rv.y;
                }
                *reinterpret_cast<float2*>(C + off) = v;
            }
        }
    }
}

// ---------------- conversions ----------------
// emb -> fp16, 4 elements per thread
__global__ __launch_bounds__(256) void conv_emb(const float* __restrict__ emb) {
    int idx = blockIdx.x * 256 + threadIdx.x;
    if (idx >= NN * DD / 4) return;
    float4 x = reinterpret_cast<const float4*>(emb)[idx];
    __half2 a, b;
    a.x = __float2half_rn(x.x); a.y = __float2half_rn(x.y);
    b.x = __float2half_rn(x.z); b.y = __float2half_rn(x.w);
    uint2 v = make_uint2(*reinterpret_cast<uint32_t*>(&a), *reinterpret_cast<uint32_t*>(&b));
    reinterpret_cast<uint2*>(g_emb)[idx] = v;
}

// weights transpose -> fp16
__global__ __launch_bounds__(256) void conv_weights(
    const float* __restrict__ WQ, const float* __restrict__ WK,
    const float* __restrict__ WV, const float* __restrict__ WO)
{
    int idx = blockIdx.x * 256 + threadIdx.x;
    if (idx >= 4 * DD * DD) return;
    int mat = idx / (DD * DD);
    int rem = idx - mat * (DD * DD);
    int n = rem / DD;
    int k = rem - n * DD;
    const float* W = (mat == 0) ? WQ : (mat == 1 ? WK : (mat == 2 ? WV : WO));
    __half h = __float2half_rn(W[(size_t)k * DD + n]);
    if (mat < 3) g_wt[(size_t)mat * DD * DD + (size_t)n * DD + k] = h;
    else         g_wo[(size_t)n * DD + k] = h;
}

// ---------------- CSR build (side stream) ----------------
__global__ __launch_bounds__(256) void zero_deg() {
    int i = blockIdx.x * 256 + threadIdx.x;
    if (i < NN) g_deg[i] = 0;
}

__global__ __launch_bounds__(256) void hist_kernel(const int* __restrict__ dst) {
    int e = blockIdx.x * 256 + threadIdx.x;
    if (e < EE) atomicAdd(&g_deg[dst[e]], 1);
}

__device__ __forceinline__ int warp_incl_scan(int x, int lane) {
#pragma unroll
    for (int off = 1; off < 32; off <<= 1) {
        int v = __shfl_up_sync(0xffffffffu, x, off);
        if (lane >= off) x += v;
    }
    return x;
}

__global__ __launch_bounds__(1024) void scanA() {
    __shared__ int swarp[32];
    const int tid = threadIdx.x;
    const int w = tid >> 5, lane = tid & 31;
    int idx = blockIdx.x * 1024 + tid;
    int x = (idx < NN) ? g_deg[idx] : 0;
    int incl = warp_incl_scan(x, lane);
    if (lane == 31) swarp[w] = incl;
    __syncthreads();
    if (w == 0) {
        int t = swarp[lane];
        t = warp_incl_scan(t, lane);
        swarp[lane] = t;
    }
    __syncthreads();
    int woff = (w > 0) ? swarp[w - 1] : 0;
    incl += woff;
    if (idx < NN) g_rowptr[idx] = incl;
    if (tid == 1023) g_blocksum[blockIdx.x] = incl;
}

__global__ __launch_bounds__(64) void scanB() {
    __shared__ int sh[64];
    const int tid = threadIdx.x;
    int v = (tid < NSCAN) ? g_blocksum[tid] : 0;
    sh[tid] = v;
    for (int off = 1; off < 64; off <<= 1) {
        __syncthreads();
        int t = (tid >= off) ? sh[tid - off] : 0;
        __syncthreads();
        sh[tid] += t;
    }
    __syncthreads();
    if (tid < NSCAN) g_blocksum[tid] = sh[tid] - v;  // exclusive
    if (tid == 63) g_rowptr[NN] = sh[63];
}

__global__ __launch_bounds__(1024) void scanC() {
    int idx = blockIdx.x * 1024 + threadIdx.x;
    if (idx >= NN) return;
    int ex = g_blocksum[blockIdx.x] + g_rowptr[idx] - g_deg[idx];
    g_rowptr[idx] = ex;
    g_cursor[idx] = ex;
}

__global__ __launch_bounds__(256) void scatter_kernel(
    const int* __restrict__ src, const int* __restrict__ dst,
    const float* __restrict__ eattr)
{
    int e = blockIdx.x * 256 + threadIdx.x;
    if (e >= EE) return;
    int t = dst[e];
    int pos = atomicAdd(&g_cursor[t], 1);
    g_esrc[pos] = src[e];
    g_eea[pos] = eattr[e];
}

// ---------------- fused attention aggregate: warp per (node, head) ----------------
__global__ __launch_bounds__(256) void node_fused(const float* __restrict__ WE) {
    const int gw = blockIdx.x * 8 + (threadIdx.x >> 5);
    const int n = gw >> 1;
    if (n >= NN) return;
    const int h = gw & 1;
    const int hb = h * DHH;
    const int lane = threadIdx.x & 31;

    float qv[6], we[6];
    const float* qrow = g_q + (size_t)n * DD + hb;
    const float* werow = WE + hb;
#pragma unroll
    for (int j = 0; j < 6; j++) {
        int d = lane + 32 * j;
        qv[j] = qrow[d];
        we[j] = werow[d];
    }

    // qe = q_h . WE_h
    float qe = 0.f;
#pragma unroll
    for (int j = 0; j < 6; j++) qe += qv[j] * we[j];
#pragma unroll
    for (int o = 16; o > 0; o >>= 1) qe += __shfl_xor_sync(0xffffffffu, qe, o);

    const int beg = g_rowptr[n];
    const int end = g_rowptr[n + 1];

    float m0 = -3.0e38f, den = 0.f, sexa = 0.f;
    float acc[6];
#pragma unroll
    for (int j = 0; j < 6; j++) acc[j] = 0.f;

    const float SCL = 0.07216878364870323f;  // 1/sqrt(192)

    for (int i = beg; i < end; i++) {
        const int s = g_esrc[i];
        const float ea = g_eea[i];
        const float* krow = g_k + (size_t)s * DD + hb;
        const float* vrow = g_v + (size_t)s * DD + hb;

        float kv[6], vv[6];
#pragma unroll
        for (int j = 0; j < 6; j++) {
            int d = lane + 32 * j;
            kv[j] = krow[d];
            vv[j] = vrow[d];
        }
        float ds = 0.f;
#pragma unroll
        for (int j = 0; j < 6; j++) ds += qv[j] * kv[j];
#pragma unroll
        for (int o = 16; o > 0; o >>= 1) ds += __shfl_xor_sync(0xffffffffu, ds, o);
        float s0 = (ds + ea * qe) * SCL;

        float nm = fmaxf(m0, s0);
        float sc = __expf(m0 - nm);
        float ex = __expf(s0 - nm);
        den = den * sc + ex;
        sexa = sexa * sc + ex * ea;
#pragma unroll
        for (int j = 0; j < 6; j++) acc[j] = acc[j] * sc + ex * vv[j];
        m0 = nm;
    }

    const float inv = 1.0f / (den + 1e-16f);
    size_t base = (size_t)n * DD + hb;
#pragma unroll
    for (int j = 0; j < 6; j++) {
        int d = lane + 32 * j;
        float o0 = (acc[j] + sexa * we[j]) * inv;
        g_agg[base + d] = __float2half_rn(o0);
    }
}

// ---------------- layernorm: warp per row, float4 ----------------
__global__ __launch_bounds__(256) void ln_kernel(
    const float* __restrict__ gw, const float* __restrict__ bw,
    float* __restrict__ out)
{
    const int n = blockIdx.x * 8 + (threadIdx.x >> 5);
    if (n >= NN) return;
    const int lane = threadIdx.x & 31;
    const float4* x = reinterpret_cast<const float4*>(g_tmp + (size_t)n * DD);
    float4 v[3];
    float su = 0.f, sq = 0.f;
#pragma unroll
    for (int j = 0; j < 3; j++) {
        v[j] = x[lane + 32 * j];
        su += v[j].x + v[j].y + v[j].z + v[j].w;
        sq += v[j].x * v[j].x + v[j].y * v[j].y + v[j].z * v[j].z + v[j].w * v[j].w;
    }
#pragma unroll
    for (int o = 16; o > 0; o >>= 1) {
        su += __shfl_xor_sync(0xffffffffu, su, o);
        sq += __shfl_xor_sync(0xffffffffu, sq, o);
    }
    float mu = su * (1.0f / DD);
    float var = sq * (1.0f / DD) - mu * mu;
    float inv = rsqrtf(var + 1e-5f);
    const float4* g4 = reinterpret_cast<const float4*>(gw);
    const float4* b4 = reinterpret_cast<const float4*>(bw);
    float4* o4 = reinterpret_cast<float4*>(out + (size_t)n * DD);
#pragma unroll
    for (int j = 0; j < 3; j++) {
        float4 g = g4[lane + 32 * j];
        float4 b = b4[lane + 32 * j];
        float4 r;
        r.x = (v[j].x - mu) * inv * g.x + b.x;
        r.y = (v[j].y - mu) * inv * g.y + b.y;
        r.z = (v[j].z - mu) * inv * g.z + b.z;
        r.w = (v[j].w - mu) * inv * g.w + b.w;
        o4[lane + 32 * j] = r;
    }
}

// ---------------- launch ----------------
extern "C" void kernel_launch(void* const* d_in, const int* in_sizes, int n_in,
                              void* d_out, int out_size)
{
    const float* emb   = (const float*)d_in[0];
    const int*   eidx  = (const int*)  d_in[1];
    const float* eattr = (const float*)d_in[2];
    const float* WQ    = (const float*)d_in[3];
    const float* WK    = (const float*)d_in[4];
    const float* WV    = (const float*)d_in[5];
    const float* WE    = (const float*)d_in[6];
    const float* WO    = (const float*)d_in[7];
    const float* ln_g  = (const float*)d_in[8];
    const float* ln_b  = (const float*)d_in[9];
    float* out = (float*)d_out;

    const int* src = eidx;
    const int* dst = eidx + EE;

    static bool inited = false;
    static cudaStream_t s_side;
    static cudaEvent_t ev_fork, ev_join, ev_w;
    if (!inited) {
        cudaFuncSetAttribute(gemm_tc, cudaFuncAttributeMaxDynamicSharedMemorySize, SM_TOTAL);
        cudaStreamCreateWithFlags(&s_side, cudaStreamNonBlocking);
        cudaEventCreateWithFlags(&ev_fork, cudaEventDisableTiming);
        cudaEventCreateWithFlags(&ev_join, cudaEventDisableTiming);
        cudaEventCreateWithFlags(&ev_w, cudaEventDisableTiming);
        inited = true;
    }

    float *dq, *dk, *dv, *dtmp;
    __half *demb, *dagg, *dwt, *dwo;
    cudaGetSymbolAddress((void**)&dq,   g_q);
    cudaGetSymbolAddress((void**)&dk,   g_k);
    cudaGetSymbolAddress((void**)&dv,   g_v);
    cudaGetSymbolAddress((void**)&dtmp, g_tmp);
    cudaGetSymbolAddress((void**)&demb, g_emb);
    cudaGetSymbolAddress((void**)&dagg, g_agg);
    cudaGetSymbolAddress((void**)&dwt,  g_wt);
    cudaGetSymbolAddress((void**)&dwo,  g_wo);

    // ---- fork: weights conversion + CSR build on side stream ----
    cudaEventRecord(ev_fork, 0);
    cudaStreamWaitEvent(s_side, ev_fork, 0);
    conv_weights<<<(4 * DD * DD + 255) / 256, 256, 0, s_side>>>(WQ, WK, WV, WO);
    cudaEventRecord(ev_w, s_side);
    zero_deg<<<(NN + 255) / 256, 256, 0, s_side>>>();
    hist_kernel<<<(EE + 255) / 256, 256, 0, s_side>>>(dst);
    scanA<<<NSCAN, 1024, 0, s_side>>>();
    scanB<<<1, 64, 0, s_side>>>();
    scanC<<<NSCAN, 1024, 0, s_side>>>();
    scatter_kernel<<<(EE + 255) / 256, 256, 0, s_side>>>(src, dst, eattr);
    cudaEventRecord(ev_join, s_side);

    // ---- main stream: emb conversion + QKV projections ----
    conv_emb<<<(NN * DD / 4 + 255) / 256, 256>>>(emb);
    cudaStreamWaitEvent(0, ev_w, 0);

    const int MT = (NN + 127) / 128;
    gemm_tc<<<dim3(9, MT), 256, SM_TOTAL>>>(demb, dwt,
                                            dq, dk, dv, NN, nullptr);

    // ---- join, then fused attention ----
    cudaStreamWaitEvent(0, ev_join, 0);
    node_fused<<<(2 * NN + 7) / 8, 256>>>(WE);

    // output projection + residual
    gemm_tc<<<dim3(3, MT), 256, SM_TOTAL>>>(dagg, dwo,
                                            dtmp, dtmp, dtmp, NN, emb);

    // layernorm -> out
    ln_kernel<<<(NN + 7) / 8, 256>>>(ln_g, ln_b, out);
}